// round 1
// baseline (speedup 1.0000x reference)
#include <cuda_runtime.h>
#include <cuda_bf16.h>
#include <math.h>

// ---------------- static problem shape ----------------
#define NTOK 8192      // B*S = 4*2048
#define DIM  1024      // D
#define NE   7         // experts
#define CAP  2574      // int(NTOK*2/7*1.1)

// ---------------- scratch (device globals; no allocs allowed) ----------------
__device__ float g_hs[NTOK * DIM];           // shared-expert hidden  (32 MB)
__device__ float g_h[NE * CAP * DIM];        // expert hidden         (74 MB)
__device__ int   g_tokE[NTOK * 2];           // per-token top-2 expert ids
__device__ float g_tokG[NTOK * 2];           // per-token top-2 gates
__device__ int   g_slotTok[NE * CAP];        // slot -> token (NTOK = empty)
__device__ float g_slotGate[NE * CAP];       // slot -> gate

// ---------------- SGEMM: 128x128 tile, BK=8, 8x8 microtile, 256 threads ----------------
#define BM 128
#define BN 128
#define BK 8
#define TM 8
#define TN 8

// MODE 0: C = relu(A@W + b), store Out
// MODE 1: C = A@W + b, store Out
// MODE 2: A gathered via slotTok (x rows), C = relu(.+b), store Out (per-expert)
// MODE 3: C = A@W + b, then atomicAdd(out[token] , gate*C) for valid slots
template <int MODE>
__global__ __launch_bounds__(256)
void sgemm_k(const float* __restrict__ A, const float* __restrict__ W,
             const float* __restrict__ bias, float* __restrict__ Out,
             int M, size_t aStride, size_t wStride, int bStride, size_t outStride,
             const int* __restrict__ slotTok, const float* __restrict__ slotGate)
{
    const int e   = blockIdx.z;
    const float* Wb = W    + (size_t)e * wStride;
    const float* Bb = bias + (size_t)e * bStride;

    __shared__ float As[BK][BM];
    __shared__ float Bs[BK][BN];

    const int tid = threadIdx.x;
    const int m0  = blockIdx.y * BM;
    const int n0  = blockIdx.x * BN;

    // A-tile load coords: 128 rows x 8 cols -> one float4 per thread
    const int rA   = tid >> 1;          // 0..127
    const int colA = (tid & 1) * 4;     // 0 or 4
    // B-tile load coords: 8 rows x 128 cols
    const int rowB = tid >> 5;          // 0..7
    const int colB = (tid & 31) * 4;    // 0..124

    const int aRow = m0 + rA;
    bool aValid = (aRow < M);
    const float* Arow;
    if (MODE == 2) {
        int tok = aValid ? __ldg(&slotTok[e * CAP + aRow]) : NTOK;
        aValid = aValid && (tok < NTOK);
        Arow = A + (size_t)(aValid ? tok : 0) * DIM;
    } else {
        Arow = A + (size_t)e * aStride + (size_t)(aValid ? aRow : 0) * DIM;
    }

    const int ty = tid >> 4;   // 0..15
    const int tx = tid & 15;   // 0..15

    float acc[TM][TN];
#pragma unroll
    for (int i = 0; i < TM; i++)
#pragma unroll
        for (int j = 0; j < TN; j++) acc[i][j] = 0.f;

    for (int kt = 0; kt < DIM; kt += BK) {
        float4 av = make_float4(0.f, 0.f, 0.f, 0.f);
        if (aValid) av = *(const float4*)(Arow + kt + colA);
        As[colA + 0][rA] = av.x;
        As[colA + 1][rA] = av.y;
        As[colA + 2][rA] = av.z;
        As[colA + 3][rA] = av.w;
        *(float4*)&Bs[rowB][colB] =
            *(const float4*)(Wb + (size_t)(kt + rowB) * DIM + n0 + colB);
        __syncthreads();

#pragma unroll
        for (int k = 0; k < BK; k++) {
            float ra[TM], rb[TN];
#pragma unroll
            for (int i = 0; i < TM; i++) ra[i] = As[k][ty * TM + i];
#pragma unroll
            for (int j = 0; j < TN; j++) rb[j] = Bs[k][tx * TN + j];
#pragma unroll
            for (int i = 0; i < TM; i++)
#pragma unroll
                for (int j = 0; j < TN; j++)
                    acc[i][j] = fmaf(ra[i], rb[j], acc[i][j]);
        }
        __syncthreads();
    }

    // epilogue
    float bv[TN];
#pragma unroll
    for (int j = 0; j < TN; j++) bv[j] = Bb[n0 + tx * TN + j];

#pragma unroll
    for (int i = 0; i < TM; i++) {
        int row = m0 + ty * TM + i;
        if (row >= M) continue;
        if (MODE == 3) {
            int tok = __ldg(&slotTok[e * CAP + row]);
            if (tok >= NTOK) continue;
            float g = __ldg(&slotGate[e * CAP + row]);
            float* orow = Out + (size_t)tok * DIM + n0 + tx * TN;
#pragma unroll
            for (int j = 0; j < TN; j++)
                atomicAdd(orow + j, g * (acc[i][j] + bv[j]));
        } else {
            float* orow = Out + (size_t)e * outStride + (size_t)row * DIM + n0 + tx * TN;
#pragma unroll
            for (int j = 0; j < TN; j++) {
                float v = acc[i][j] + bv[j];
                if (MODE != 1) v = fmaxf(v, 0.f);
                orow[j] = v;
            }
        }
    }
}

// ---------------- router: warp per token, fp32 exact-ish ----------------
__global__ void router_k(const float* __restrict__ x, const float* __restrict__ noise,
                         const float* __restrict__ Wr, const float* __restrict__ br,
                         const float* __restrict__ Wn, const float* __restrict__ bn,
                         int* __restrict__ tokE, float* __restrict__ tokG)
{
    int gw   = (blockIdx.x * blockDim.x + threadIdx.x) >> 5;
    int lane = threadIdx.x & 31;
    if (gw >= NTOK) return;
    const float* xr = x + (size_t)gw * DIM;

    float aR[NE], aN[NE];
#pragma unroll
    for (int e = 0; e < NE; e++) { aR[e] = 0.f; aN[e] = 0.f; }

    for (int kk = 0; kk < DIM / 32; ++kk) {
        int   k  = kk * 32 + lane;
        float xv = xr[k];                      // coalesced
        const float* wr = Wr + (size_t)k * NE; // 28KB, L1-resident
        const float* wn = Wn + (size_t)k * NE;
#pragma unroll
        for (int e = 0; e < NE; e++) {
            aR[e] = fmaf(xv, __ldg(wr + e), aR[e]);
            aN[e] = fmaf(xv, __ldg(wn + e), aN[e]);
        }
    }
#pragma unroll
    for (int off = 16; off; off >>= 1) {
#pragma unroll
        for (int e = 0; e < NE; e++) {
            aR[e] += __shfl_xor_sync(0xffffffffu, aR[e], off);
            aN[e] += __shfl_xor_sync(0xffffffffu, aN[e], off);
        }
    }
    if (lane == 0) {
        float v1 = -1e30f, v2 = -1e30f;
        int   i1 = 0, i2 = 0;
#pragma unroll
        for (int e = 0; e < NE; e++) {
            float ln = aN[e] + bn[e];
            float sp = fmaxf(ln, 0.f) + log1pf(expf(-fabsf(ln)));  // softplus, jax-match
            float v  = aR[e] + br[e] + noise[(size_t)gw * NE + e] * sp;
            if (v > v1)      { v2 = v1; i2 = i1; v1 = v; i1 = e; } // ties -> lower index, matches jax top_k
            else if (v > v2) { v2 = v;  i2 = e; }
        }
        float d   = expf(v2 - v1);
        float inv = 1.f / (1.f + d);
        tokE[2 * gw]     = i1;  tokE[2 * gw + 1] = i2;
        tokG[2 * gw]     = inv; tokG[2 * gw + 1] = d * inv;
    }
}

// ---------------- load-balance loss (deterministic single-block reduce) ----------------
__global__ void lbl_k(const int* __restrict__ tokE, const float* __restrict__ tokG,
                      float* __restrict__ out, int writeLbl)
{
    __shared__ float sf[1024];
    __shared__ float sums[2 * NE];
    int tid = threadIdx.x;
    float pg[NE], pc[NE];
#pragma unroll
    for (int e = 0; e < NE; e++) { pg[e] = 0.f; pc[e] = 0.f; }
    for (int t = tid; t < NTOK; t += 1024) {
        int   e0 = tokE[2 * t], e1 = tokE[2 * t + 1];
        float g0 = tokG[2 * t], g1 = tokG[2 * t + 1];
#pragma unroll
        for (int e = 0; e < NE; e++) {
            pg[e] += (e0 == e ? g0 : 0.f) + (e1 == e ? g1 : 0.f);
            pc[e] += (e0 == e ? 1.f : 0.f) + (e1 == e ? 1.f : 0.f);
        }
    }
    for (int e = 0; e < NE; e++) {
        sf[tid] = pg[e]; __syncthreads();
        for (int off = 512; off; off >>= 1) { if (tid < off) sf[tid] += sf[tid + off]; __syncthreads(); }
        if (tid == 0) sums[e] = sf[0];
        __syncthreads();
        sf[tid] = pc[e]; __syncthreads();
        for (int off = 512; off; off >>= 1) { if (tid < off) sf[tid] += sf[tid + off]; __syncthreads(); }
        if (tid == 0) sums[NE + e] = sf[0];
        __syncthreads();
    }
    if (tid == 0 && writeLbl) {
        float l = 0.f;
        for (int e = 0; e < NE; e++)
            l += (sums[e] / (float)NTOK) * (sums[NE + e] / (float)NTOK);
        out[(size_t)NTOK * DIM] = l * (float)NE;
    }
}

// ---------------- capacity dispatch: one block per expert, FCFS scan ----------------
__global__ void scan_k(const int* __restrict__ tokE, const float* __restrict__ tokG,
                       int* __restrict__ slotTok, float* __restrict__ slotGate)
{
    const int e   = blockIdx.x;
    const int tid = threadIdx.x;      // 1024 threads
    __shared__ int s[1024];

    for (int c = tid; c < CAP; c += 1024) {
        slotTok[e * CAP + c]  = NTOK;
        slotGate[e * CAP + c] = 0.f;
    }
    __syncthreads();

    int base = 0;
    for (int tile = 0; tile < NTOK; tile += 1024) {
        int t  = tile + tid;
        int e0 = tokE[2 * t], e1 = tokE[2 * t + 1];
        int flag = (e0 == e) || (e1 == e);
        s[tid] = flag; __syncthreads();
        // Hillis-Steele inclusive scan
        for (int off = 1; off < 1024; off <<= 1) {
            int v   = s[tid];
            int add = (tid >= off) ? s[tid - off] : 0;
            __syncthreads();
            s[tid] = v + add;
            __syncthreads();
        }
        int pos = base + s[tid] - 1;
        if (flag && pos < CAP) {
            slotTok[e * CAP + pos]  = t;
            slotGate[e * CAP + pos] = (e0 == e) ? tokG[2 * t] : tokG[2 * t + 1];
        }
        base += s[1023];
        __syncthreads();
    }
}

// ---------------- host ----------------
extern "C" void kernel_launch(void* const* d_in, const int* in_sizes, int n_in,
                              void* d_out, int out_size)
{
    const float* x   = (const float*)d_in[0];
    const float* noi = (const float*)d_in[1];
    const float* Wr  = (const float*)d_in[2];
    const float* br  = (const float*)d_in[3];
    const float* Wn  = (const float*)d_in[4];
    const float* bn  = (const float*)d_in[5];
    const float* W1  = (const float*)d_in[6];
    const float* b1  = (const float*)d_in[7];
    const float* W2  = (const float*)d_in[8];
    const float* b2  = (const float*)d_in[9];
    const float* Ws1 = (const float*)d_in[10];
    const float* bs1 = (const float*)d_in[11];
    const float* Ws2 = (const float*)d_in[12];
    const float* bs2 = (const float*)d_in[13];
    float* out = (float*)d_out;

    float *hs, *hx, *tokG, *slotGate;
    int *tokE, *slotTok;
    cudaGetSymbolAddress((void**)&hs,       g_hs);
    cudaGetSymbolAddress((void**)&hx,       g_h);
    cudaGetSymbolAddress((void**)&tokE,     g_tokE);
    cudaGetSymbolAddress((void**)&tokG,     g_tokG);
    cudaGetSymbolAddress((void**)&slotTok,  g_slotTok);
    cudaGetSymbolAddress((void**)&slotGate, g_slotGate);

    dim3 blk(256);
    dim3 gridS(DIM / BN, NTOK / BM, 1);                 // 8 x 64
    dim3 gridE(DIM / BN, (CAP + BM - 1) / BM, NE);      // 8 x 21 x 7

    // shared expert: out = relu(x@Ws1+bs1)@Ws2 + bs2  (writes d_out base)
    sgemm_k<0><<<gridS, blk>>>(x,  Ws1, bs1, hs,  NTOK, 0, 0, 0, 0, nullptr, nullptr);
    sgemm_k<1><<<gridS, blk>>>(hs, Ws2, bs2, out, NTOK, 0, 0, 0, 0, nullptr, nullptr);

    // router + aux loss + capacity dispatch
    router_k<<<1024, 256>>>(x, noi, Wr, br, Wn, bn, tokE, tokG);
    lbl_k<<<1, 1024>>>(tokE, tokG, out, (out_size > NTOK * DIM) ? 1 : 0);
    scan_k<<<NE, 1024>>>(tokE, tokG, slotTok, slotGate);

    // experts: h = relu(gather(x)@W1[e]+b1[e]);  out += gate * (h@W2[e]+b2[e])
    sgemm_k<2><<<gridE, blk>>>(x,  W1, b1, hx,  CAP, 0,
                               (size_t)DIM * DIM, DIM, (size_t)CAP * DIM, slotTok, nullptr);
    sgemm_k<3><<<gridE, blk>>>(hx, W2, b2, out, CAP, (size_t)CAP * DIM,
                               (size_t)DIM * DIM, DIM, 0, slotTok, slotGate);
    (void)in_sizes; (void)n_in;
}

// round 3
// speedup vs baseline: 1.7255x; 1.7255x over previous
#include <cuda_runtime.h>
#include <cuda_bf16.h>
#include <math.h>
#include <stdint.h>

// ---------------- static problem shape ----------------
#define NTOK 8192
#define DIM  1024
#define NE   7
#define CAP  2574            // int(NTOK*2/7*1.1)

typedef __nv_bfloat16 bf16;

// ---------------- scratch (device globals) ----------------
__device__ bf16  g_xh [NTOK * DIM];
__device__ bf16  g_xl [NTOK * DIM];
__device__ bf16  g_hsh[NTOK * DIM];
__device__ bf16  g_hsl[NTOK * DIM];
__device__ bf16  g_hh [NE * CAP * DIM];
__device__ bf16  g_hl [NE * CAP * DIM];
__device__ bf16  g_w1th[NE * DIM * DIM];     // W1^T split  [e][n][k]
__device__ bf16  g_w1tl[NE * DIM * DIM];
__device__ bf16  g_w2th[NE * DIM * DIM];
__device__ bf16  g_w2tl[NE * DIM * DIM];
__device__ bf16  g_ws1th[DIM * DIM];
__device__ bf16  g_ws1tl[DIM * DIM];
__device__ bf16  g_ws2th[DIM * DIM];
__device__ bf16  g_ws2tl[DIM * DIM];
__device__ int   g_tokE[NTOK * 2];
__device__ float g_tokG[NTOK * 2];
__device__ int   g_slotTok[NE * CAP];
__device__ float g_slotGate[NE * CAP];

// ---------------- PTX helpers (all baseline ISA, no sm_103a-only features) ----------------
__device__ __forceinline__ uint32_t smem_u32(const void* p) {
    uint32_t a;
    asm("{ .reg .u64 t; cvta.to.shared.u64 t, %1; cvt.u32.u64 %0, t; }" : "=r"(a) : "l"(p));
    return a;
}
#define SW128(x) ((x) ^ (((x) >> 3) & 0x70))
#define CP16(dst, src) asm volatile("cp.async.cg.shared.global [%0], [%1], 16;" :: "r"(dst), "l"(src))
#define CP_COMMIT() asm volatile("cp.async.commit_group;" ::: "memory")
#define CP_WAIT(n)  asm volatile("cp.async.wait_group %0;" :: "n"(n) : "memory")

#define LDSM4(R, a) \
    asm volatile("ldmatrix.sync.aligned.m8n8.x4.shared.b16 {%0,%1,%2,%3}, [%4];" \
        : "=r"((R)[0]), "=r"((R)[1]), "=r"((R)[2]), "=r"((R)[3]) : "r"(a))

#define MMA(C, A, B0, B1) \
    asm volatile("mma.sync.aligned.m16n8k16.row.col.f32.bf16.bf16.f32 " \
        "{%0,%1,%2,%3}, {%4,%5,%6,%7}, {%8,%9}, {%0,%1,%2,%3};" \
        : "+f"((C)[0]), "+f"((C)[1]), "+f"((C)[2]), "+f"((C)[3]) \
        : "r"((A)[0]), "r"((A)[1]), "r"((A)[2]), "r"((A)[3]), "r"(B0), "r"(B1))

// ---------------- smem layout ----------------
// stage s at s*65536: Ah 16K | Al 16K | Bh 16K | Bl 16K  (128 rows x 128B each)
#define STG_BYTES 65536u
#define SMEM_BYTES (2 * 65536)
#define NCHUNK (DIM / 64)

// ---------------- GEMM: 128x128 CTA tile, BK=64, mma.sync bf16 3-term ----------------
// AMODE: 0 = direct rows, 1 = gather x rows via slotTok, 2 = expert-local hidden rows
// EPI:   0 = relu + bf16-split store to Oh/Ol, 1 = fp32 store OutF, 2 = gate*atomicAdd OutF
template <int AMODE, int EPI>
__global__ __launch_bounds__(256, 1)
void moe_gemm(const bf16* __restrict__ Ah_, const bf16* __restrict__ Al_,
              const bf16* __restrict__ Bh_, const bf16* __restrict__ Bl_,
              const float* __restrict__ bias, float* __restrict__ OutF,
              bf16* __restrict__ Oh, bf16* __restrict__ Ol,
              int M, const int* __restrict__ slotTok, const float* __restrict__ slotGate)
{
    extern __shared__ char smem[];
    const int tid  = threadIdx.x;
    const int wid  = tid >> 5;
    const int lane = tid & 31;
    const int e    = blockIdx.z;
    const int m0   = blockIdx.y * 128;
    const int n0   = blockIdx.x * 128;
    const uint32_t sb = smem_u32(smem);

    const float* biasE = bias + e * DIM;

    // ---- per-thread global source rows for the fill ----
    const int rA   = tid & 127;       // row within tile (A) / n-row (B^T)
    const int half = tid >> 7;        // 0 = hi, 1 = lo
    size_t aRowG;
    if (AMODE == 0) {
        aRowG = (size_t)(m0 + rA);
    } else if (AMODE == 1) {
        int slot = m0 + rA;
        int tok  = (slot < CAP) ? __ldg(&slotTok[e * CAP + slot]) : NTOK;
        if (tok >= NTOK) tok = 0;
        aRowG = (size_t)tok;
    } else {
        int r = m0 + rA; if (r > CAP - 1) r = CAP - 1;
        aRowG = (size_t)e * CAP + r;
    }
    const bf16* aSrc = (half ? Al_ : Ah_) + aRowG * DIM;
    const bf16* bSrc = (half ? Bl_ : Bh_) + ((size_t)e << 20) + (size_t)(n0 + rA) * DIM;

    const uint32_t aDstBase = half * 16384u;
    const uint32_t bDstBase = 32768u + half * 16384u;
    const uint32_t rowOff   = (uint32_t)rA * 128u;

    auto fill = [&](int c) {
        uint32_t stg = sb + (uint32_t)(c & 1) * STG_BYTES;
        const bf16* sA = aSrc + c * 64;
        const bf16* sB = bSrc + c * 64;
#pragma unroll
        for (int s = 0; s < 8; s++) {
            uint32_t off = SW128(rowOff + s * 16u);
            CP16(stg + aDstBase + off, sA + s * 8);
            CP16(stg + bDstBase + off, sB + s * 8);
        }
        CP_COMMIT();
    };

    // ---- warp tiling: 2 (m) x 4 (n); warp tile 64x32 ----
    const int wm = (wid & 1) * 64;
    const int wn = (wid >> 1) * 32;

    // ldmatrix per-lane coords
    const uint32_t aRowL = (uint32_t)(wm + ((lane >> 3) & 1) * 8 + (lane & 7));
    const uint32_t aOffL = (uint32_t)((lane >> 4) * 16);
    const uint32_t bRowL = (uint32_t)(wn + ((lane >> 4) & 1) * 8 + (lane & 7));
    const uint32_t bOffL = (uint32_t)(((lane >> 3) & 1) * 16);

    float acc[4][4][4];
#pragma unroll
    for (int i = 0; i < 4; i++)
#pragma unroll
        for (int j = 0; j < 4; j++)
#pragma unroll
            for (int q = 0; q < 4; q++) acc[i][j][q] = 0.f;

    fill(0);
    for (int c = 0; c < NCHUNK; c++) {
        if (c + 1 < NCHUNK) { fill(c + 1); CP_WAIT(1); }
        else                { CP_WAIT(0); }
        __syncthreads();

        uint32_t stg = sb + (uint32_t)(c & 1) * STG_BYTES;
#pragma unroll
        for (int ks = 0; ks < 4; ks++) {
            uint32_t bh[4][2], bl[4][2];
#pragma unroll
            for (int bt = 0; bt < 2; bt++) {
                uint32_t r4[4];
                uint32_t boff = SW128((bRowL + bt * 16u) * 128u + bOffL + ks * 32u);
                LDSM4(r4, stg + 32768u + boff);
                bh[bt * 2][0] = r4[0]; bh[bt * 2][1] = r4[1];
                bh[bt * 2 + 1][0] = r4[2]; bh[bt * 2 + 1][1] = r4[3];
                LDSM4(r4, stg + 49152u + boff);
                bl[bt * 2][0] = r4[0]; bl[bt * 2][1] = r4[1];
                bl[bt * 2 + 1][0] = r4[2]; bl[bt * 2 + 1][1] = r4[3];
            }
#pragma unroll
            for (int mt = 0; mt < 4; mt++) {
                uint32_t ah[4], al[4];
                uint32_t aoff = SW128((aRowL + mt * 16u) * 128u + aOffL + ks * 32u);
                LDSM4(ah, stg + aoff);
                LDSM4(al, stg + 16384u + aoff);
#pragma unroll
                for (int nt = 0; nt < 4; nt++) MMA(acc[mt][nt], ah, bh[nt][0], bh[nt][1]);
#pragma unroll
                for (int nt = 0; nt < 4; nt++) MMA(acc[mt][nt], ah, bl[nt][0], bl[nt][1]);
#pragma unroll
                for (int nt = 0; nt < 4; nt++) MMA(acc[mt][nt], al, bh[nt][0], bh[nt][1]);
            }
        }
        __syncthreads();
    }

    // ---- epilogue ----
#pragma unroll
    for (int mt = 0; mt < 4; mt++) {
#pragma unroll
        for (int h = 0; h < 2; h++) {
            int rloc = wm + mt * 16 + (lane >> 2) + h * 8;
            int grow = m0 + rloc;

            bool   valid = true;
            size_t obase = 0;
            float  gate  = 0.f;
            if (EPI == 0) {
                if (AMODE == 0) {
                    obase = (size_t)grow * DIM;
                    valid = (grow < M);
                } else {
                    valid = (grow < CAP);
                    obase = ((size_t)e * CAP + (valid ? grow : 0)) * DIM;
                }
            } else if (EPI == 1) {
                valid = (grow < M);
                obase = (size_t)grow * DIM;
            } else {
                valid = false;
                if (grow < CAP) {
                    int tok = __ldg(&slotTok[e * CAP + grow]);
                    if (tok < NTOK) {
                        gate  = __ldg(&slotGate[e * CAP + grow]);
                        obase = (size_t)tok * DIM;
                        valid = true;
                    }
                }
            }
            if (!valid) continue;

#pragma unroll
            for (int nt = 0; nt < 4; nt++) {
                int nc = n0 + wn + nt * 8 + (lane & 3) * 2;
                float v0 = acc[mt][nt][h * 2 + 0] + __ldg(&biasE[nc]);
                float v1 = acc[mt][nt][h * 2 + 1] + __ldg(&biasE[nc + 1]);
                if (EPI == 0) {
                    v0 = fmaxf(v0, 0.f); v1 = fmaxf(v1, 0.f);
                    bf16 h0 = __float2bfloat16_rn(v0);
                    bf16 h1 = __float2bfloat16_rn(v1);
                    bf16 l0 = __float2bfloat16_rn(v0 - __bfloat162float(h0));
                    bf16 l1 = __float2bfloat16_rn(v1 - __bfloat162float(h1));
                    uint32_t hp = (uint32_t)*(ushort*)&h0 | ((uint32_t)*(ushort*)&h1 << 16);
                    uint32_t lp = (uint32_t)*(ushort*)&l0 | ((uint32_t)*(ushort*)&l1 << 16);
                    *reinterpret_cast<uint32_t*>(Oh + obase + nc) = hp;
                    *reinterpret_cast<uint32_t*>(Ol + obase + nc) = lp;
                } else if (EPI == 1) {
                    float2 v = make_float2(v0, v1);
                    *reinterpret_cast<float2*>(OutF + obase + nc) = v;
                } else {
                    atomicAdd(OutF + obase + nc,     gate * v0);
                    atomicAdd(OutF + obase + nc + 1, gate * v1);
                }
            }
        }
    }
}

// ---------------- prep: split x into bf16 hi/lo ----------------
__global__ void prep_x_k(const float* __restrict__ x, bf16* __restrict__ xh, bf16* __restrict__ xl)
{
    int i = (blockIdx.x * blockDim.x + threadIdx.x) * 4;
    float4 v = *reinterpret_cast<const float4*>(x + i);
    bf16 h0 = __float2bfloat16_rn(v.x), h1 = __float2bfloat16_rn(v.y);
    bf16 h2 = __float2bfloat16_rn(v.z), h3 = __float2bfloat16_rn(v.w);
    bf16 l0 = __float2bfloat16_rn(v.x - __bfloat162float(h0));
    bf16 l1 = __float2bfloat16_rn(v.y - __bfloat162float(h1));
    bf16 l2 = __float2bfloat16_rn(v.z - __bfloat162float(h2));
    bf16 l3 = __float2bfloat16_rn(v.w - __bfloat162float(h3));
    ushort4 hp = make_ushort4(*(ushort*)&h0, *(ushort*)&h1, *(ushort*)&h2, *(ushort*)&h3);
    ushort4 lp = make_ushort4(*(ushort*)&l0, *(ushort*)&l1, *(ushort*)&l2, *(ushort*)&l3);
    *reinterpret_cast<ushort4*>(xh + i) = hp;
    *reinterpret_cast<ushort4*>(xl + i) = lp;
}

// ---------------- prep: transpose + split weights ----------------
__global__ void prep_w_k(const float* __restrict__ W, bf16* __restrict__ Th, bf16* __restrict__ Tl)
{
    __shared__ float tile[32][33];
    const size_t mo = (size_t)blockIdx.z << 20;
    const float* Wm = W + mo;
    int n0 = blockIdx.x * 32, k0 = blockIdx.y * 32;
    for (int r = threadIdx.y; r < 32; r += 8)
        tile[r][threadIdx.x] = Wm[(size_t)(k0 + r) * DIM + n0 + threadIdx.x];
    __syncthreads();
    for (int r = threadIdx.y; r < 32; r += 8) {
        float v = tile[threadIdx.x][r];
        bf16 h = __float2bfloat16_rn(v);
        bf16 l = __float2bfloat16_rn(v - __bfloat162float(h));
        size_t o = mo + (size_t)(n0 + r) * DIM + k0 + threadIdx.x;
        Th[o] = h; Tl[o] = l;
    }
}

// ---------------- router ----------------
__global__ void router_k(const float* __restrict__ x, const float* __restrict__ noise,
                         const float* __restrict__ Wr, const float* __restrict__ br,
                         const float* __restrict__ Wn, const float* __restrict__ bn,
                         int* __restrict__ tokE, float* __restrict__ tokG)
{
    int gw   = (blockIdx.x * blockDim.x + threadIdx.x) >> 5;
    int lane = threadIdx.x & 31;
    if (gw >= NTOK) return;
    const float* xr = x + (size_t)gw * DIM;
    float aR[NE], aN[NE];
#pragma unroll
    for (int e = 0; e < NE; e++) { aR[e] = 0.f; aN[e] = 0.f; }
    for (int kk = 0; kk < DIM / 32; ++kk) {
        int   k  = kk * 32 + lane;
        float xv = xr[k];
        const float* wr = Wr + (size_t)k * NE;
        const float* wn = Wn + (size_t)k * NE;
#pragma unroll
        for (int e = 0; e < NE; e++) {
            aR[e] = fmaf(xv, __ldg(wr + e), aR[e]);
            aN[e] = fmaf(xv, __ldg(wn + e), aN[e]);
        }
    }
#pragma unroll
    for (int off = 16; off; off >>= 1) {
#pragma unroll
        for (int e = 0; e < NE; e++) {
            aR[e] += __shfl_xor_sync(0xffffffffu, aR[e], off);
            aN[e] += __shfl_xor_sync(0xffffffffu, aN[e], off);
        }
    }
    if (lane == 0) {
        float v1 = -1e30f, v2 = -1e30f; int i1 = 0, i2 = 0;
#pragma unroll
        for (int e = 0; e < NE; e++) {
            float ln = aN[e] + bn[e];
            float sp = fmaxf(ln, 0.f) + log1pf(expf(-fabsf(ln)));
            float v  = aR[e] + br[e] + noise[(size_t)gw * NE + e] * sp;
            if (v > v1)      { v2 = v1; i2 = i1; v1 = v; i1 = e; }
            else if (v > v2) { v2 = v;  i2 = e; }
        }
        float d = expf(v2 - v1);
        float inv = 1.f / (1.f + d);
        tokE[2 * gw] = i1; tokE[2 * gw + 1] = i2;
        tokG[2 * gw] = inv; tokG[2 * gw + 1] = d * inv;
    }
}

// ---------------- load-balance loss ----------------
__global__ void lbl_k(const int* __restrict__ tokE, const float* __restrict__ tokG,
                      float* __restrict__ out, int writeLbl)
{
    __shared__ float sf[1024];
    __shared__ float sums[2 * NE];
    int tid = threadIdx.x;
    float pg[NE], pc[NE];
#pragma unroll
    for (int e = 0; e < NE; e++) { pg[e] = 0.f; pc[e] = 0.f; }
    for (int t = tid; t < NTOK; t += 1024) {
        int   e0 = tokE[2 * t], e1 = tokE[2 * t + 1];
        float g0 = tokG[2 * t], g1 = tokG[2 * t + 1];
#pragma unroll
        for (int e = 0; e < NE; e++) {
            pg[e] += (e0 == e ? g0 : 0.f) + (e1 == e ? g1 : 0.f);
            pc[e] += (e0 == e ? 1.f : 0.f) + (e1 == e ? 1.f : 0.f);
        }
    }
    for (int e = 0; e < NE; e++) {
        sf[tid] = pg[e]; __syncthreads();
        for (int off = 512; off; off >>= 1) { if (tid < off) sf[tid] += sf[tid + off]; __syncthreads(); }
        if (tid == 0) sums[e] = sf[0];
        __syncthreads();
        sf[tid] = pc[e]; __syncthreads();
        for (int off = 512; off; off >>= 1) { if (tid < off) sf[tid] += sf[tid + off]; __syncthreads(); }
        if (tid == 0) sums[NE + e] = sf[0];
        __syncthreads();
    }
    if (tid == 0 && writeLbl) {
        float l = 0.f;
        for (int e = 0; e < NE; e++)
            l += (sums[e] / (float)NTOK) * (sums[NE + e] / (float)NTOK);
        out[(size_t)NTOK * DIM] = l * (float)NE;
    }
}

// ---------------- capacity dispatch ----------------
__global__ void scan_k(const int* __restrict__ tokE, const float* __restrict__ tokG,
                       int* __restrict__ slotTok, float* __restrict__ slotGate)
{
    const int e = blockIdx.x, tid = threadIdx.x;
    __shared__ int s[1024];
    for (int c = tid; c < CAP; c += 1024) {
        slotTok[e * CAP + c]  = NTOK;
        slotGate[e * CAP + c] = 0.f;
    }
    __syncthreads();
    int base = 0;
    for (int tile = 0; tile < NTOK; tile += 1024) {
        int t  = tile + tid;
        int e0 = tokE[2 * t], e1 = tokE[2 * t + 1];
        int flag = (e0 == e) || (e1 == e);
        s[tid] = flag; __syncthreads();
        for (int off = 1; off < 1024; off <<= 1) {
            int v = s[tid];
            int add = (tid >= off) ? s[tid - off] : 0;
            __syncthreads();
            s[tid] = v + add;
            __syncthreads();
        }
        int pos = base + s[tid] - 1;
        if (flag && pos < CAP) {
            slotTok[e * CAP + pos]  = t;
            slotGate[e * CAP + pos] = (e0 == e) ? tokG[2 * t] : tokG[2 * t + 1];
        }
        base += s[1023];
        __syncthreads();
    }
}

// ---------------- host ----------------
extern "C" void kernel_launch(void* const* d_in, const int* in_sizes, int n_in,
                              void* d_out, int out_size)
{
    const float* x   = (const float*)d_in[0];
    const float* noi = (const float*)d_in[1];
    const float* Wr  = (const float*)d_in[2];
    const float* br  = (const float*)d_in[3];
    const float* Wn  = (const float*)d_in[4];
    const float* bn  = (const float*)d_in[5];
    const float* W1  = (const float*)d_in[6];
    const float* b1  = (const float*)d_in[7];
    const float* W2  = (const float*)d_in[8];
    const float* b2  = (const float*)d_in[9];
    const float* Ws1 = (const float*)d_in[10];
    const float* bs1 = (const float*)d_in[11];
    const float* Ws2 = (const float*)d_in[12];
    const float* bs2 = (const float*)d_in[13];
    float* out = (float*)d_out;

    bf16 *xh, *xl, *hsh, *hsl, *hh, *hl;
    bf16 *w1th, *w1tl, *w2th, *w2tl, *ws1th, *ws1tl, *ws2th, *ws2tl;
    int *tokE, *slotTok; float *tokG, *slotGate;
    cudaGetSymbolAddress((void**)&xh, g_xh);     cudaGetSymbolAddress((void**)&xl, g_xl);
    cudaGetSymbolAddress((void**)&hsh, g_hsh);   cudaGetSymbolAddress((void**)&hsl, g_hsl);
    cudaGetSymbolAddress((void**)&hh, g_hh);     cudaGetSymbolAddress((void**)&hl, g_hl);
    cudaGetSymbolAddress((void**)&w1th, g_w1th); cudaGetSymbolAddress((void**)&w1tl, g_w1tl);
    cudaGetSymbolAddress((void**)&w2th, g_w2th); cudaGetSymbolAddress((void**)&w2tl, g_w2tl);
    cudaGetSymbolAddress((void**)&ws1th, g_ws1th); cudaGetSymbolAddress((void**)&ws1tl, g_ws1tl);
    cudaGetSymbolAddress((void**)&ws2th, g_ws2th); cudaGetSymbolAddress((void**)&ws2tl, g_ws2tl);
    cudaGetSymbolAddress((void**)&tokE, g_tokE); cudaGetSymbolAddress((void**)&tokG, g_tokG);
    cudaGetSymbolAddress((void**)&slotTok, g_slotTok); cudaGetSymbolAddress((void**)&slotGate, g_slotGate);

    cudaFuncSetAttribute(moe_gemm<0,0>, cudaFuncAttributeMaxDynamicSharedMemorySize, SMEM_BYTES);
    cudaFuncSetAttribute(moe_gemm<0,1>, cudaFuncAttributeMaxDynamicSharedMemorySize, SMEM_BYTES);
    cudaFuncSetAttribute(moe_gemm<1,0>, cudaFuncAttributeMaxDynamicSharedMemorySize, SMEM_BYTES);
    cudaFuncSetAttribute(moe_gemm<2,2>, cudaFuncAttributeMaxDynamicSharedMemorySize, SMEM_BYTES);

    // prep
    prep_x_k<<<NTOK * DIM / (256 * 4), 256>>>(x, xh, xl);
    dim3 tb(32, 8);
    prep_w_k<<<dim3(32, 32, 1),  tb>>>(Ws1, ws1th, ws1tl);
    prep_w_k<<<dim3(32, 32, 1),  tb>>>(Ws2, ws2th, ws2tl);
    prep_w_k<<<dim3(32, 32, NE), tb>>>(W1, w1th, w1tl);
    prep_w_k<<<dim3(32, 32, NE), tb>>>(W2, w2th, w2tl);

    // router / dispatch
    router_k<<<1024, 256>>>(x, noi, Wr, br, Wn, bn, tokE, tokG);
    lbl_k<<<1, 1024>>>(tokE, tokG, out, (out_size > NTOK * DIM) ? 1 : 0);
    scan_k<<<NE, 1024>>>(tokE, tokG, slotTok, slotGate);

    // GEMMs
    dim3 gS(DIM / 128, NTOK / 128, 1);              // 8 x 64
    dim3 gE(DIM / 128, (CAP + 127) / 128, NE);      // 8 x 21 x 7
    moe_gemm<0,0><<<gS, 256, SMEM_BYTES>>>(xh, xl, ws1th, ws1tl, bs1, nullptr, hsh, hsl,
                                           NTOK, nullptr, nullptr);
    moe_gemm<0,1><<<gS, 256, SMEM_BYTES>>>(hsh, hsl, ws2th, ws2tl, bs2, out, nullptr, nullptr,
                                           NTOK, nullptr, nullptr);
    moe_gemm<1,0><<<gE, 256, SMEM_BYTES>>>(xh, xl, w1th, w1tl, b1, nullptr, hh, hl,
                                           CAP, slotTok, nullptr);
    moe_gemm<2,2><<<gE, 256, SMEM_BYTES>>>(hh, hl, w2th, w2tl, b2, out, nullptr, nullptr,
                                           CAP, slotTok, slotGate);
    (void)in_sizes; (void)n_in;
}

// round 4
// speedup vs baseline: 1.9694x; 1.1414x over previous
#include <cuda_runtime.h>
#include <cuda_bf16.h>
#include <math.h>
#include <stdint.h>

// ---------------- static problem shape ----------------
#define NTOK 8192
#define DIM  1024
#define NE   7
#define CAP  2574            // int(NTOK*2/7*1.1)

typedef __nv_bfloat16 bf16;

// ---------------- scratch (device globals) ----------------
__device__ bf16  g_xh [NTOK * DIM];
__device__ bf16  g_xl [NTOK * DIM];
__device__ bf16  g_hsh[NTOK * DIM];
__device__ bf16  g_hsl[NTOK * DIM];
__device__ bf16  g_hh [NE * CAP * DIM];
__device__ bf16  g_hl [NE * CAP * DIM];
__device__ bf16  g_w1th[NE * DIM * DIM];     // W1^T split  [e][n][k]
__device__ bf16  g_w1tl[NE * DIM * DIM];
__device__ bf16  g_w2th[NE * DIM * DIM];
__device__ bf16  g_w2tl[NE * DIM * DIM];
__device__ bf16  g_ws1th[DIM * DIM];
__device__ bf16  g_ws1tl[DIM * DIM];
__device__ bf16  g_ws2th[DIM * DIM];
__device__ bf16  g_ws2tl[DIM * DIM];
__device__ int   g_tokE[NTOK * 2];
__device__ float g_tokG[NTOK * 2];
__device__ int   g_slotTok[NE * CAP];
__device__ float g_slotGate[NE * CAP];

// ---------------- PTX helpers (baseline ISA only) ----------------
__device__ __forceinline__ uint32_t smem_u32(const void* p) {
    uint32_t a;
    asm("{ .reg .u64 t; cvta.to.shared.u64 t, %1; cvt.u32.u64 %0, t; }" : "=r"(a) : "l"(p));
    return a;
}
#define SW64(x) ((x) ^ (((x) >> 3) & 0x30))
#define CP16(dst, src) asm volatile("cp.async.cg.shared.global [%0], [%1], 16;" :: "r"(dst), "l"(src))
#define CP_COMMIT() asm volatile("cp.async.commit_group;" ::: "memory")
#define CP_WAIT(n)  asm volatile("cp.async.wait_group %0;" :: "n"(n) : "memory")

#define LDSM4(R, a) \
    asm volatile("ldmatrix.sync.aligned.m8n8.x4.shared.b16 {%0,%1,%2,%3}, [%4];" \
        : "=r"((R)[0]), "=r"((R)[1]), "=r"((R)[2]), "=r"((R)[3]) : "r"(a))

#define MMA(C, A, B0, B1) \
    asm volatile("mma.sync.aligned.m16n8k16.row.col.f32.bf16.bf16.f32 " \
        "{%0,%1,%2,%3}, {%4,%5,%6,%7}, {%8,%9}, {%0,%1,%2,%3};" \
        : "+f"((C)[0]), "+f"((C)[1]), "+f"((C)[2]), "+f"((C)[3]) \
        : "r"((A)[0]), "r"((A)[1]), "r"((A)[2]), "r"((A)[3]), "r"(B0), "r"(B1))

// ---------------- smem: 3 stages, each 32KB: Ah 8K | Al 8K | Bh 8K | Bl 8K ----------------
// rows are 64B (BK=32 bf16), SW64 swizzle
#define STG_BYTES 32768u
#define NSTAGE    3
#define SMEM_BYTES (NSTAGE * 32768)
#define NCHUNK    (DIM / 32)

// ---------------- GEMM: 128x128 CTA tile, BK=32, mma.sync bf16 3-term ----------------
// AMODE: 0 = direct rows, 1 = gather x rows via slotTok, 2 = expert-local hidden rows
// EPI:   0 = relu + bf16-split store Oh/Ol, 1 = fp32 store OutF, 2 = gate*atomicAdd OutF
template <int AMODE, int EPI>
__global__ __launch_bounds__(256, 2)
void moe_gemm(const bf16* __restrict__ Ah_, const bf16* __restrict__ Al_,
              const bf16* __restrict__ Bh_, const bf16* __restrict__ Bl_,
              const float* __restrict__ bias, float* __restrict__ OutF,
              bf16* __restrict__ Oh, bf16* __restrict__ Ol,
              int M, const int* __restrict__ slotTok, const float* __restrict__ slotGate)
{
    extern __shared__ char smem[];
    const int tid  = threadIdx.x;
    const int wid  = tid >> 5;
    const int lane = tid & 31;
    const int e    = blockIdx.z;
    const int m0   = blockIdx.y * 128;
    const int n0   = blockIdx.x * 128;
    const uint32_t sb = smem_u32(smem);

    const float* biasE = bias + e * DIM;

    // ---- per-thread global source rows for the fill ----
    const int rA   = tid & 127;
    const int half = tid >> 7;        // 0 = hi, 1 = lo
    size_t aRowG;
    if (AMODE == 0) {
        aRowG = (size_t)(m0 + rA);
    } else if (AMODE == 1) {
        int slot = m0 + rA;
        int tok  = (slot < CAP) ? __ldg(&slotTok[e * CAP + slot]) : NTOK;
        if (tok >= NTOK) tok = 0;
        aRowG = (size_t)tok;
    } else {
        int r = m0 + rA; if (r > CAP - 1) r = CAP - 1;
        aRowG = (size_t)e * CAP + r;
    }
    const bf16* aSrc = (half ? Al_ : Ah_) + aRowG * DIM;
    const bf16* bSrc = (half ? Bl_ : Bh_) + ((size_t)e << 20) + (size_t)(n0 + rA) * DIM;

    const uint32_t aDstBase = half * 8192u;
    const uint32_t bDstBase = 16384u + half * 8192u;
    const uint32_t rowOff   = (uint32_t)rA * 64u;

    auto fill = [&](int c) {
        uint32_t stg = sb + (uint32_t)(c % NSTAGE) * STG_BYTES;
        const bf16* sA = aSrc + c * 32;
        const bf16* sB = bSrc + c * 32;
#pragma unroll
        for (int s = 0; s < 4; s++) {
            uint32_t off = SW64(rowOff + s * 16u);
            CP16(stg + aDstBase + off, sA + s * 8);
            CP16(stg + bDstBase + off, sB + s * 8);
        }
        CP_COMMIT();
    };

    // ---- warp tiling: 2 (m) x 4 (n); warp tile 64x32 ----
    const int wm = (wid & 1) * 64;
    const int wn = (wid >> 1) * 32;

    const uint32_t aRowL = (uint32_t)(wm + ((lane >> 3) & 1) * 8 + (lane & 7));
    const uint32_t aOffL = (uint32_t)((lane >> 4) * 16);
    const uint32_t bRowL = (uint32_t)(wn + ((lane >> 4) & 1) * 8 + (lane & 7));
    const uint32_t bOffL = (uint32_t)(((lane >> 3) & 1) * 16);

    float acc[4][4][4];
#pragma unroll
    for (int i = 0; i < 4; i++)
#pragma unroll
        for (int j = 0; j < 4; j++)
#pragma unroll
            for (int q = 0; q < 4; q++) acc[i][j][q] = 0.f;

    fill(0);
    fill(1);
#pragma unroll 1
    for (int c = 0; c < NCHUNK; c++) {
        if (c == NCHUNK - 1) { CP_WAIT(0); } else { CP_WAIT(1); }
        __syncthreads();
        if (c + 2 < NCHUNK) fill(c + 2);

        uint32_t stg = sb + (uint32_t)(c % NSTAGE) * STG_BYTES;
#pragma unroll
        for (int ks = 0; ks < 2; ks++) {
            uint32_t bh[4][2], bl[4][2];
#pragma unroll
            for (int bt = 0; bt < 2; bt++) {
                uint32_t r4[4];
                uint32_t boff = SW64((bRowL + bt * 16u) * 64u + bOffL + ks * 32u);
                LDSM4(r4, stg + 16384u + boff);
                bh[bt * 2][0] = r4[0]; bh[bt * 2][1] = r4[1];
                bh[bt * 2 + 1][0] = r4[2]; bh[bt * 2 + 1][1] = r4[3];
                LDSM4(r4, stg + 24576u + boff);
                bl[bt * 2][0] = r4[0]; bl[bt * 2][1] = r4[1];
                bl[bt * 2 + 1][0] = r4[2]; bl[bt * 2 + 1][1] = r4[3];
            }
#pragma unroll
            for (int mt = 0; mt < 4; mt++) {
                uint32_t ah[4], al[4];
                uint32_t aoff = SW64((aRowL + mt * 16u) * 64u + aOffL + ks * 32u);
                LDSM4(ah, stg + aoff);
                LDSM4(al, stg + 8192u + aoff);
#pragma unroll
                for (int nt = 0; nt < 4; nt++) MMA(acc[mt][nt], ah, bh[nt][0], bh[nt][1]);
#pragma unroll
                for (int nt = 0; nt < 4; nt++) MMA(acc[mt][nt], ah, bl[nt][0], bl[nt][1]);
#pragma unroll
                for (int nt = 0; nt < 4; nt++) MMA(acc[mt][nt], al, bh[nt][0], bh[nt][1]);
            }
        }
    }

    // ---- epilogue ----
#pragma unroll
    for (int mt = 0; mt < 4; mt++) {
#pragma unroll
        for (int h = 0; h < 2; h++) {
            int rloc = wm + mt * 16 + (lane >> 2) + h * 8;
            int grow = m0 + rloc;

            bool   valid = true;
            size_t obase = 0;
            float  gate  = 0.f;
            if (EPI == 0) {
                if (AMODE == 0) {
                    obase = (size_t)grow * DIM;
                    valid = (grow < M);
                } else {
                    valid = (grow < CAP);
                    obase = ((size_t)e * CAP + (valid ? grow : 0)) * DIM;
                }
            } else if (EPI == 1) {
                valid = (grow < M);
                obase = (size_t)grow * DIM;
            } else {
                valid = false;
                if (grow < CAP) {
                    int tok = __ldg(&slotTok[e * CAP + grow]);
                    if (tok < NTOK) {
                        gate  = __ldg(&slotGate[e * CAP + grow]);
                        obase = (size_t)tok * DIM;
                        valid = true;
                    }
                }
            }
            if (!valid) continue;

#pragma unroll
            for (int nt = 0; nt < 4; nt++) {
                int nc = n0 + wn + nt * 8 + (lane & 3) * 2;
                float v0 = acc[mt][nt][h * 2 + 0] + __ldg(&biasE[nc]);
                float v1 = acc[mt][nt][h * 2 + 1] + __ldg(&biasE[nc + 1]);
                if (EPI == 0) {
                    v0 = fmaxf(v0, 0.f); v1 = fmaxf(v1, 0.f);
                    bf16 h0 = __float2bfloat16_rn(v0);
                    bf16 h1 = __float2bfloat16_rn(v1);
                    bf16 l0 = __float2bfloat16_rn(v0 - __bfloat162float(h0));
                    bf16 l1 = __float2bfloat16_rn(v1 - __bfloat162float(h1));
                    uint32_t hp = (uint32_t)*(ushort*)&h0 | ((uint32_t)*(ushort*)&h1 << 16);
                    uint32_t lp = (uint32_t)*(ushort*)&l0 | ((uint32_t)*(ushort*)&l1 << 16);
                    *reinterpret_cast<uint32_t*>(Oh + obase + nc) = hp;
                    *reinterpret_cast<uint32_t*>(Ol + obase + nc) = lp;
                } else if (EPI == 1) {
                    float2 v = make_float2(v0, v1);
                    *reinterpret_cast<float2*>(OutF + obase + nc) = v;
                } else {
                    atomicAdd(OutF + obase + nc,     gate * v0);
                    atomicAdd(OutF + obase + nc + 1, gate * v1);
                }
            }
        }
    }
}

// ---------------- prep: split x into bf16 hi/lo ----------------
__global__ void prep_x_k(const float* __restrict__ x, bf16* __restrict__ xh, bf16* __restrict__ xl)
{
    int i = (blockIdx.x * blockDim.x + threadIdx.x) * 4;
    float4 v = *reinterpret_cast<const float4*>(x + i);
    bf16 h0 = __float2bfloat16_rn(v.x), h1 = __float2bfloat16_rn(v.y);
    bf16 h2 = __float2bfloat16_rn(v.z), h3 = __float2bfloat16_rn(v.w);
    bf16 l0 = __float2bfloat16_rn(v.x - __bfloat162float(h0));
    bf16 l1 = __float2bfloat16_rn(v.y - __bfloat162float(h1));
    bf16 l2 = __float2bfloat16_rn(v.z - __bfloat162float(h2));
    bf16 l3 = __float2bfloat16_rn(v.w - __bfloat162float(h3));
    ushort4 hp = make_ushort4(*(ushort*)&h0, *(ushort*)&h1, *(ushort*)&h2, *(ushort*)&h3);
    ushort4 lp = make_ushort4(*(ushort*)&l0, *(ushort*)&l1, *(ushort*)&l2, *(ushort*)&l3);
    *reinterpret_cast<ushort4*>(xh + i) = hp;
    *reinterpret_cast<ushort4*>(xl + i) = lp;
}

// ---------------- prep: transpose + split weights ----------------
__global__ void prep_w_k(const float* __restrict__ W, bf16* __restrict__ Th, bf16* __restrict__ Tl)
{
    __shared__ float tile[32][33];
    const size_t mo = (size_t)blockIdx.z << 20;
    const float* Wm = W + mo;
    int n0 = blockIdx.x * 32, k0 = blockIdx.y * 32;
    for (int r = threadIdx.y; r < 32; r += 8)
        tile[r][threadIdx.x] = Wm[(size_t)(k0 + r) * DIM + n0 + threadIdx.x];
    __syncthreads();
    for (int r = threadIdx.y; r < 32; r += 8) {
        float v = tile[threadIdx.x][r];
        bf16 h = __float2bfloat16_rn(v);
        bf16 l = __float2bfloat16_rn(v - __bfloat162float(h));
        size_t o = mo + (size_t)(n0 + r) * DIM + k0 + threadIdx.x;
        Th[o] = h; Tl[o] = l;
    }
}

// ---------------- router ----------------
__global__ void router_k(const float* __restrict__ x, const float* __restrict__ noise,
                         const float* __restrict__ Wr, const float* __restrict__ br,
                         const float* __restrict__ Wn, const float* __restrict__ bn,
                         int* __restrict__ tokE, float* __restrict__ tokG)
{
    int gw   = (blockIdx.x * blockDim.x + threadIdx.x) >> 5;
    int lane = threadIdx.x & 31;
    if (gw >= NTOK) return;
    const float* xr = x + (size_t)gw * DIM;
    float aR[NE], aN[NE];
#pragma unroll
    for (int e = 0; e < NE; e++) { aR[e] = 0.f; aN[e] = 0.f; }
    for (int kk = 0; kk < DIM / 32; ++kk) {
        int   k  = kk * 32 + lane;
        float xv = xr[k];
        const float* wr = Wr + (size_t)k * NE;
        const float* wn = Wn + (size_t)k * NE;
#pragma unroll
        for (int e = 0; e < NE; e++) {
            aR[e] = fmaf(xv, __ldg(wr + e), aR[e]);
            aN[e] = fmaf(xv, __ldg(wn + e), aN[e]);
        }
    }
#pragma unroll
    for (int off = 16; off; off >>= 1) {
#pragma unroll
        for (int e = 0; e < NE; e++) {
            aR[e] += __shfl_xor_sync(0xffffffffu, aR[e], off);
            aN[e] += __shfl_xor_sync(0xffffffffu, aN[e], off);
        }
    }
    if (lane == 0) {
        float v1 = -1e30f, v2 = -1e30f; int i1 = 0, i2 = 0;
#pragma unroll
        for (int e = 0; e < NE; e++) {
            float ln = aN[e] + bn[e];
            float sp = fmaxf(ln, 0.f) + log1pf(expf(-fabsf(ln)));
            float v  = aR[e] + br[e] + noise[(size_t)gw * NE + e] * sp;
            if (v > v1)      { v2 = v1; i2 = i1; v1 = v; i1 = e; }
            else if (v > v2) { v2 = v;  i2 = e; }
        }
        float d = expf(v2 - v1);
        float inv = 1.f / (1.f + d);
        tokE[2 * gw] = i1; tokE[2 * gw + 1] = i2;
        tokG[2 * gw] = inv; tokG[2 * gw + 1] = d * inv;
    }
}

// ---------------- load-balance loss: 1024 threads, warp-shuffle reduce ----------------
__global__ void lbl_k(const int* __restrict__ tokE, const float* __restrict__ tokG,
                      float* __restrict__ out, int writeLbl)
{
    __shared__ float ws[32][2 * NE];
    int tid = threadIdx.x, lane = tid & 31, wid = tid >> 5;
    float pg[NE], pc[NE];
#pragma unroll
    for (int e = 0; e < NE; e++) { pg[e] = 0.f; pc[e] = 0.f; }
    for (int t = tid; t < NTOK; t += 1024) {
        int   e0 = tokE[2 * t], e1 = tokE[2 * t + 1];
        float g0 = tokG[2 * t], g1 = tokG[2 * t + 1];
#pragma unroll
        for (int e = 0; e < NE; e++) {
            pg[e] += (e0 == e ? g0 : 0.f) + (e1 == e ? g1 : 0.f);
            pc[e] += (e0 == e ? 1.f : 0.f) + (e1 == e ? 1.f : 0.f);
        }
    }
#pragma unroll
    for (int off = 16; off; off >>= 1) {
#pragma unroll
        for (int e = 0; e < NE; e++) {
            pg[e] += __shfl_xor_sync(0xffffffffu, pg[e], off);
            pc[e] += __shfl_xor_sync(0xffffffffu, pc[e], off);
        }
    }
    if (lane == 0) {
#pragma unroll
        for (int e = 0; e < NE; e++) { ws[wid][e] = pg[e]; ws[wid][NE + e] = pc[e]; }
    }
    __syncthreads();
    if (tid == 0 && writeLbl) {
        float sums[2 * NE];
#pragma unroll
        for (int j = 0; j < 2 * NE; j++) {
            float s = 0.f;
            for (int w = 0; w < 32; w++) s += ws[w][j];
            sums[j] = s;
        }
        float l = 0.f;
        for (int e = 0; e < NE; e++)
            l += (sums[e] / (float)NTOK) * (sums[NE + e] / (float)NTOK);
        out[(size_t)NTOK * DIM] = l * (float)NE;
    }
}

// ---------------- capacity dispatch: warp-ballot FCFS scan ----------------
__global__ void scan_k(const int* __restrict__ tokE, const float* __restrict__ tokG,
                       int* __restrict__ slotTok, float* __restrict__ slotGate)
{
    const int e = blockIdx.x, tid = threadIdx.x;   // 1024 threads = 32 warps
    const int lane = tid & 31, wid = tid >> 5;
    __shared__ int wsum[32];
    __shared__ int wbase[32];
    __shared__ int blksum;

    for (int c = tid; c < CAP; c += 1024) {
        slotTok[e * CAP + c]  = NTOK;
        slotGate[e * CAP + c] = 0.f;
    }
    __syncthreads();

    int base = 0;
    for (int tile = 0; tile < NTOK; tile += 1024) {
        int t  = tile + tid;
        int e0 = tokE[2 * t], e1 = tokE[2 * t + 1];
        int flag = (e0 == e) || (e1 == e);
        uint32_t b = __ballot_sync(0xffffffffu, flag);
        int lpre = __popc(b & ((1u << lane) - 1));
        if (lane == 0) wsum[wid] = __popc(b);
        __syncthreads();
        if (wid == 0) {
            int v = wsum[lane];
            int inc = v;
#pragma unroll
            for (int off = 1; off < 32; off <<= 1) {
                int y = __shfl_up_sync(0xffffffffu, inc, off);
                if (lane >= off) inc += y;
            }
            wbase[lane] = inc - v;
            if (lane == 31) blksum = inc;
        }
        __syncthreads();
        int pos = base + wbase[wid] + lpre;
        if (flag && pos < CAP) {
            slotTok[e * CAP + pos]  = t;
            slotGate[e * CAP + pos] = (e0 == e) ? tokG[2 * t] : tokG[2 * t + 1];
        }
        base += blksum;
        __syncthreads();
    }
}

// ---------------- host ----------------
extern "C" void kernel_launch(void* const* d_in, const int* in_sizes, int n_in,
                              void* d_out, int out_size)
{
    const float* x   = (const float*)d_in[0];
    const float* noi = (const float*)d_in[1];
    const float* Wr  = (const float*)d_in[2];
    const float* br  = (const float*)d_in[3];
    const float* Wn  = (const float*)d_in[4];
    const float* bn  = (const float*)d_in[5];
    const float* W1  = (const float*)d_in[6];
    const float* b1  = (const float*)d_in[7];
    const float* W2  = (const float*)d_in[8];
    const float* b2  = (const float*)d_in[9];
    const float* Ws1 = (const float*)d_in[10];
    const float* bs1 = (const float*)d_in[11];
    const float* Ws2 = (const float*)d_in[12];
    const float* bs2 = (const float*)d_in[13];
    float* out = (float*)d_out;

    bf16 *xh, *xl, *hsh, *hsl, *hh, *hl;
    bf16 *w1th, *w1tl, *w2th, *w2tl, *ws1th, *ws1tl, *ws2th, *ws2tl;
    int *tokE, *slotTok; float *tokG, *slotGate;
    cudaGetSymbolAddress((void**)&xh, g_xh);     cudaGetSymbolAddress((void**)&xl, g_xl);
    cudaGetSymbolAddress((void**)&hsh, g_hsh);   cudaGetSymbolAddress((void**)&hsl, g_hsl);
    cudaGetSymbolAddress((void**)&hh, g_hh);     cudaGetSymbolAddress((void**)&hl, g_hl);
    cudaGetSymbolAddress((void**)&w1th, g_w1th); cudaGetSymbolAddress((void**)&w1tl, g_w1tl);
    cudaGetSymbolAddress((void**)&w2th, g_w2th); cudaGetSymbolAddress((void**)&w2tl, g_w2tl);
    cudaGetSymbolAddress((void**)&ws1th, g_ws1th); cudaGetSymbolAddress((void**)&ws1tl, g_ws1tl);
    cudaGetSymbolAddress((void**)&ws2th, g_ws2th); cudaGetSymbolAddress((void**)&ws2tl, g_ws2tl);
    cudaGetSymbolAddress((void**)&tokE, g_tokE); cudaGetSymbolAddress((void**)&tokG, g_tokG);
    cudaGetSymbolAddress((void**)&slotTok, g_slotTok); cudaGetSymbolAddress((void**)&slotGate, g_slotGate);

    cudaFuncSetAttribute(moe_gemm<0,0>, cudaFuncAttributeMaxDynamicSharedMemorySize, SMEM_BYTES);
    cudaFuncSetAttribute(moe_gemm<0,1>, cudaFuncAttributeMaxDynamicSharedMemorySize, SMEM_BYTES);
    cudaFuncSetAttribute(moe_gemm<1,0>, cudaFuncAttributeMaxDynamicSharedMemorySize, SMEM_BYTES);
    cudaFuncSetAttribute(moe_gemm<2,2>, cudaFuncAttributeMaxDynamicSharedMemorySize, SMEM_BYTES);

    // prep
    prep_x_k<<<NTOK * DIM / (256 * 4), 256>>>(x, xh, xl);
    dim3 tb(32, 8);
    prep_w_k<<<dim3(32, 32, 1),  tb>>>(Ws1, ws1th, ws1tl);
    prep_w_k<<<dim3(32, 32, 1),  tb>>>(Ws2, ws2th, ws2tl);
    prep_w_k<<<dim3(32, 32, NE), tb>>>(W1, w1th, w1tl);
    prep_w_k<<<dim3(32, 32, NE), tb>>>(W2, w2th, w2tl);

    // router / dispatch
    router_k<<<1024, 256>>>(x, noi, Wr, br, Wn, bn, tokE, tokG);
    lbl_k<<<1, 1024>>>(tokE, tokG, out, (out_size > NTOK * DIM) ? 1 : 0);
    scan_k<<<NE, 1024>>>(tokE, tokG, slotTok, slotGate);

    // GEMMs
    dim3 gS(DIM / 128, NTOK / 128, 1);              // 8 x 64
    dim3 gE(DIM / 128, (CAP + 127) / 128, NE);      // 8 x 21 x 7
    moe_gemm<0,0><<<gS, 256, SMEM_BYTES>>>(xh, xl, ws1th, ws1tl, bs1, nullptr, hsh, hsl,
                                           NTOK, nullptr, nullptr);
    moe_gemm<0,1><<<gS, 256, SMEM_BYTES>>>(hsh, hsl, ws2th, ws2tl, bs2, out, nullptr, nullptr,
                                           NTOK, nullptr, nullptr);
    moe_gemm<1,0><<<gE, 256, SMEM_BYTES>>>(xh, xl, w1th, w1tl, b1, nullptr, hh, hl,
                                           CAP, slotTok, nullptr);
    moe_gemm<2,2><<<gE, 256, SMEM_BYTES>>>(hh, hl, w2th, w2tl, b2, out, nullptr, nullptr,
                                           CAP, slotTok, slotGate);
    (void)in_sizes; (void)n_in;
}

// round 5
// speedup vs baseline: 2.9198x; 1.4825x over previous
#include <cuda_runtime.h>
#include <cuda_fp16.h>
#include <math.h>
#include <stdint.h>

// ---------------- static problem shape ----------------
#define NTOK 8192
#define DIM  1024
#define NE   7
#define CAP  2574            // int(NTOK*2/7*1.1)

// ---------------- scratch (device globals) ----------------
__device__ __half g_xf [NTOK * DIM];          // x rounded to fp16
__device__ __half g_hsf[NTOK * DIM];          // shared hidden fp16
__device__ __half g_hef[NE * CAP * DIM];      // expert hidden fp16
__device__ __half g_w1th[NE * DIM * DIM];     // (32*W1)^T hi  [e][n][k]
__device__ __half g_w1tl[NE * DIM * DIM];     // (32*W1)^T lo
__device__ __half g_w2th[NE * DIM * DIM];
__device__ __half g_w2tl[NE * DIM * DIM];
__device__ __half g_ws1th[DIM * DIM];
__device__ __half g_ws1tl[DIM * DIM];
__device__ __half g_ws2th[DIM * DIM];
__device__ __half g_ws2tl[DIM * DIM];
__device__ int   g_tokE[NTOK * 2];
__device__ float g_tokG[NTOK * 2];
__device__ int   g_slotTok[NE * CAP];
__device__ float g_slotGate[NE * CAP];

// ---------------- PTX helpers (baseline ISA only) ----------------
__device__ __forceinline__ uint32_t smem_u32(const void* p) {
    uint32_t a;
    asm("{ .reg .u64 t; cvta.to.shared.u64 t, %1; cvt.u32.u64 %0, t; }" : "=r"(a) : "l"(p));
    return a;
}
#define SW64(x) ((x) ^ (((x) >> 3) & 0x30))
#define CP16(dst, src) asm volatile("cp.async.cg.shared.global [%0], [%1], 16;" :: "r"(dst), "l"(src))
#define CP_COMMIT() asm volatile("cp.async.commit_group;" ::: "memory")
#define CP_WAIT(n)  asm volatile("cp.async.wait_group %0;" :: "n"(n) : "memory")

#define LDSM4(R, a) \
    asm volatile("ldmatrix.sync.aligned.m8n8.x4.shared.b16 {%0,%1,%2,%3}, [%4];" \
        : "=r"((R)[0]), "=r"((R)[1]), "=r"((R)[2]), "=r"((R)[3]) : "r"(a))

#define MMA(C, A, B0, B1) \
    asm volatile("mma.sync.aligned.m16n8k16.row.col.f32.f16.f16.f32 " \
        "{%0,%1,%2,%3}, {%4,%5,%6,%7}, {%8,%9}, {%0,%1,%2,%3};" \
        : "+f"((C)[0]), "+f"((C)[1]), "+f"((C)[2]), "+f"((C)[3]) \
        : "r"((A)[0]), "r"((A)[1]), "r"((A)[2]), "r"((A)[3]), "r"(B0), "r"(B1))

#define WSCALE    32.0f
#define WSCALE_INV 0.03125f

// ---------------- smem: 4 stages x 24KB: A 8K | Bh 8K | Bl 8K ----------------
#define STG_BYTES 24576u
#define NSTAGE    4
#define SMEM_BYTES (NSTAGE * 24576)
#define NCHUNK    (DIM / 32)

// ---------------- GEMM: 128x128 CTA tile, BK=32, mma.sync fp16 2-term ----------------
// AMODE: 0 = direct rows of Af, 1 = gather x rows via slotTok, 2 = expert-local hidden rows
// EPI:   0 = relu + fp16 store Oh, 1 = fp32 store OutF, 2 = gate*atomicAdd OutF
template <int AMODE, int EPI>
__global__ __launch_bounds__(256, 2)
void moe_gemm(const __half* __restrict__ Af, const __half* __restrict__ Bh_,
              const __half* __restrict__ Bl_,
              const float* __restrict__ bias, float* __restrict__ OutF,
              __half* __restrict__ Oh,
              int M, const int* __restrict__ slotTok, const float* __restrict__ slotGate)
{
    extern __shared__ char smem[];
    const int tid  = threadIdx.x;
    const int wid  = tid >> 5;
    const int lane = tid & 31;
    const int e    = blockIdx.z;
    const int m0   = blockIdx.y * 128;
    const int n0   = blockIdx.x * 128;
    const uint32_t sb = smem_u32(smem);

    const float* biasE = bias + e * DIM;

    // ---- per-thread global source rows for the fill ----
    const int rA = tid & 127;
    size_t aRowG;
    if (AMODE == 0) {
        aRowG = (size_t)(m0 + rA);
    } else if (AMODE == 1) {
        int slot = m0 + rA;
        int tok  = (slot < CAP) ? __ldg(&slotTok[e * CAP + slot]) : NTOK;
        if (tok >= NTOK) tok = 0;
        aRowG = (size_t)tok;
    } else {
        int r = m0 + rA; if (r > CAP - 1) r = CAP - 1;
        aRowG = (size_t)e * CAP + r;
    }
    const __half* aSrc  = Af + aRowG * DIM;                                  // threads 0-127
    const __half* bhSrc = Bh_ + ((size_t)e << 20) + (size_t)(n0 + rA) * DIM; // threads 128-255
    const int  rBl   = tid >> 1;                 // Bl row 0..127
    const int  h2    = tid & 1;                  // which 32B half
    const __half* blSrc = Bl_ + ((size_t)e << 20) + (size_t)(n0 + rBl) * DIM;
    const uint32_t rowOff  = (uint32_t)rA * 64u;
    const uint32_t rowOffL = (uint32_t)rBl * 64u;

    auto fill = [&](int c) {
        uint32_t stg = sb + (uint32_t)(c & (NSTAGE - 1)) * STG_BYTES;
        if (tid < 128) {
            const __half* s = aSrc + c * 32;
#pragma unroll
            for (int q = 0; q < 4; q++)
                CP16(stg + SW64(rowOff + q * 16u), s + q * 8);
        } else {
            const __half* s = bhSrc + c * 32;
#pragma unroll
            for (int q = 0; q < 4; q++)
                CP16(stg + 8192u + SW64(rowOff + q * 16u), s + q * 8);
        }
        const __half* sl = blSrc + c * 32 + h2 * 16;
#pragma unroll
        for (int q = 0; q < 2; q++)
            CP16(stg + 16384u + SW64(rowOffL + h2 * 32u + q * 16u), sl + q * 8);
        CP_COMMIT();
    };

    // ---- warp tiling: 2 (m) x 4 (n); warp tile 64x32 ----
    const int wm = (wid & 1) * 64;
    const int wn = (wid >> 1) * 32;

    const uint32_t aRowL = (uint32_t)(wm + ((lane >> 3) & 1) * 8 + (lane & 7));
    const uint32_t aOffL = (uint32_t)((lane >> 4) * 16);
    const uint32_t bRowL = (uint32_t)(wn + ((lane >> 4) & 1) * 8 + (lane & 7));
    const uint32_t bOffL = (uint32_t)(((lane >> 3) & 1) * 16);

    float acc[4][4][4];
#pragma unroll
    for (int i = 0; i < 4; i++)
#pragma unroll
        for (int j = 0; j < 4; j++)
#pragma unroll
            for (int q = 0; q < 4; q++) acc[i][j][q] = 0.f;

    fill(0); fill(1); fill(2);
#pragma unroll 1
    for (int c = 0; c < NCHUNK; c++) {
        if (c < NCHUNK - 2)      { CP_WAIT(2); }
        else if (c == NCHUNK - 2){ CP_WAIT(1); }
        else                     { CP_WAIT(0); }
        __syncthreads();
        if (c + 3 < NCHUNK) fill(c + 3);

        uint32_t stg = sb + (uint32_t)(c & (NSTAGE - 1)) * STG_BYTES;
#pragma unroll
        for (int ks = 0; ks < 2; ks++) {
            uint32_t bh[4][2], bl[4][2];
#pragma unroll
            for (int bt = 0; bt < 2; bt++) {
                uint32_t r4[4];
                uint32_t boff = SW64((bRowL + bt * 16u) * 64u + bOffL + ks * 32u);
                LDSM4(r4, stg + 8192u + boff);
                bh[bt * 2][0] = r4[0]; bh[bt * 2][1] = r4[1];
                bh[bt * 2 + 1][0] = r4[2]; bh[bt * 2 + 1][1] = r4[3];
                LDSM4(r4, stg + 16384u + boff);
                bl[bt * 2][0] = r4[0]; bl[bt * 2][1] = r4[1];
                bl[bt * 2 + 1][0] = r4[2]; bl[bt * 2 + 1][1] = r4[3];
            }
#pragma unroll
            for (int mt = 0; mt < 4; mt++) {
                uint32_t a4[4];
                uint32_t aoff = SW64((aRowL + mt * 16u) * 64u + aOffL + ks * 32u);
                LDSM4(a4, stg + aoff);
#pragma unroll
                for (int nt = 0; nt < 4; nt++) MMA(acc[mt][nt], a4, bh[nt][0], bh[nt][1]);
#pragma unroll
                for (int nt = 0; nt < 4; nt++) MMA(acc[mt][nt], a4, bl[nt][0], bl[nt][1]);
            }
        }
    }

    // ---- epilogue (acc holds 32 * A@W; unscale, bias, act, route) ----
#pragma unroll
    for (int mt = 0; mt < 4; mt++) {
#pragma unroll
        for (int h = 0; h < 2; h++) {
            int rloc = wm + mt * 16 + (lane >> 2) + h * 8;
            int grow = m0 + rloc;

            bool   valid = true;
            size_t obase = 0;
            float  gate  = 0.f;
            if (EPI == 0) {
                if (AMODE == 0) {
                    obase = (size_t)grow * DIM;
                    valid = (grow < M);
                } else {
                    valid = (grow < CAP);
                    obase = ((size_t)e * CAP + (valid ? grow : 0)) * DIM;
                }
            } else if (EPI == 1) {
                valid = (grow < M);
                obase = (size_t)grow * DIM;
            } else {
                valid = false;
                if (grow < CAP) {
                    int tok = __ldg(&slotTok[e * CAP + grow]);
                    if (tok < NTOK) {
                        gate  = __ldg(&slotGate[e * CAP + grow]);
                        obase = (size_t)tok * DIM;
                        valid = true;
                    }
                }
            }
            if (!valid) continue;

#pragma unroll
            for (int nt = 0; nt < 4; nt++) {
                int nc = n0 + wn + nt * 8 + (lane & 3) * 2;
                float v0 = acc[mt][nt][h * 2 + 0] * WSCALE_INV + __ldg(&biasE[nc]);
                float v1 = acc[mt][nt][h * 2 + 1] * WSCALE_INV + __ldg(&biasE[nc + 1]);
                if (EPI == 0) {
                    v0 = fmaxf(v0, 0.f); v1 = fmaxf(v1, 0.f);
                    __half h0 = __float2half_rn(v0);
                    __half h1 = __float2half_rn(v1);
                    uint32_t hp = (uint32_t)*(ushort*)&h0 | ((uint32_t)*(ushort*)&h1 << 16);
                    *reinterpret_cast<uint32_t*>(Oh + obase + nc) = hp;
                } else if (EPI == 1) {
                    float2 v = make_float2(v0, v1);
                    *reinterpret_cast<float2*>(OutF + obase + nc) = v;
                } else {
                    atomicAdd(OutF + obase + nc,     gate * v0);
                    atomicAdd(OutF + obase + nc + 1, gate * v1);
                }
            }
        }
    }
}

// ---------------- prep: round x to fp16 ----------------
__global__ void prep_x_k(const float* __restrict__ x, __half* __restrict__ xf)
{
    int i = (blockIdx.x * blockDim.x + threadIdx.x) * 4;
    float4 v = *reinterpret_cast<const float4*>(x + i);
    __half h0 = __float2half_rn(v.x), h1 = __float2half_rn(v.y);
    __half h2 = __float2half_rn(v.z), h3 = __float2half_rn(v.w);
    ushort4 p = make_ushort4(*(ushort*)&h0, *(ushort*)&h1, *(ushort*)&h2, *(ushort*)&h3);
    *reinterpret_cast<ushort4*>(xf + i) = p;
}

// ---------------- prep: transpose + scale + fp16-split weights ----------------
__global__ void prep_w_k(const float* __restrict__ W, __half* __restrict__ Th, __half* __restrict__ Tl)
{
    __shared__ float tile[32][33];
    const size_t mo = (size_t)blockIdx.z << 20;
    const float* Wm = W + mo;
    int n0 = blockIdx.x * 32, k0 = blockIdx.y * 32;
    for (int r = threadIdx.y; r < 32; r += 8)
        tile[r][threadIdx.x] = Wm[(size_t)(k0 + r) * DIM + n0 + threadIdx.x];
    __syncthreads();
    for (int r = threadIdx.y; r < 32; r += 8) {
        float v = tile[threadIdx.x][r] * WSCALE;
        __half h = __float2half_rn(v);
        __half l = __float2half_rn(v - __half2float(h));
        size_t o = mo + (size_t)(n0 + r) * DIM + k0 + threadIdx.x;
        Th[o] = h; Tl[o] = l;
    }
}

// ---------------- router ----------------
__global__ void router_k(const float* __restrict__ x, const float* __restrict__ noise,
                         const float* __restrict__ Wr, const float* __restrict__ br,
                         const float* __restrict__ Wn, const float* __restrict__ bn,
                         int* __restrict__ tokE, float* __restrict__ tokG)
{
    int gw   = (blockIdx.x * blockDim.x + threadIdx.x) >> 5;
    int lane = threadIdx.x & 31;
    if (gw >= NTOK) return;
    const float* xr = x + (size_t)gw * DIM;
    float aR[NE], aN[NE];
#pragma unroll
    for (int e = 0; e < NE; e++) { aR[e] = 0.f; aN[e] = 0.f; }
    for (int kk = 0; kk < DIM / 32; ++kk) {
        int   k  = kk * 32 + lane;
        float xv = xr[k];
        const float* wr = Wr + (size_t)k * NE;
        const float* wn = Wn + (size_t)k * NE;
#pragma unroll
        for (int e = 0; e < NE; e++) {
            aR[e] = fmaf(xv, __ldg(wr + e), aR[e]);
            aN[e] = fmaf(xv, __ldg(wn + e), aN[e]);
        }
    }
#pragma unroll
    for (int off = 16; off; off >>= 1) {
#pragma unroll
        for (int e = 0; e < NE; e++) {
            aR[e] += __shfl_xor_sync(0xffffffffu, aR[e], off);
            aN[e] += __shfl_xor_sync(0xffffffffu, aN[e], off);
        }
    }
    if (lane == 0) {
        float v1 = -1e30f, v2 = -1e30f; int i1 = 0, i2 = 0;
#pragma unroll
        for (int e = 0; e < NE; e++) {
            float ln = aN[e] + bn[e];
            float sp = fmaxf(ln, 0.f) + log1pf(expf(-fabsf(ln)));
            float v  = aR[e] + br[e] + noise[(size_t)gw * NE + e] * sp;
            if (v > v1)      { v2 = v1; i2 = i1; v1 = v; i1 = e; }
            else if (v > v2) { v2 = v;  i2 = e; }
        }
        float d = expf(v2 - v1);
        float inv = 1.f / (1.f + d);
        tokE[2 * gw] = i1; tokE[2 * gw + 1] = i2;
        tokG[2 * gw] = inv; tokG[2 * gw + 1] = d * inv;
    }
}

// ---------------- load-balance loss ----------------
__global__ void lbl_k(const int* __restrict__ tokE, const float* __restrict__ tokG,
                      float* __restrict__ out, int writeLbl)
{
    __shared__ float ws[32][2 * NE];
    int tid = threadIdx.x, lane = tid & 31, wid = tid >> 5;
    float pg[NE], pc[NE];
#pragma unroll
    for (int e = 0; e < NE; e++) { pg[e] = 0.f; pc[e] = 0.f; }
    for (int t = tid; t < NTOK; t += 1024) {
        int   e0 = tokE[2 * t], e1 = tokE[2 * t + 1];
        float g0 = tokG[2 * t], g1 = tokG[2 * t + 1];
#pragma unroll
        for (int e = 0; e < NE; e++) {
            pg[e] += (e0 == e ? g0 : 0.f) + (e1 == e ? g1 : 0.f);
            pc[e] += (e0 == e ? 1.f : 0.f) + (e1 == e ? 1.f : 0.f);
        }
    }
#pragma unroll
    for (int off = 16; off; off >>= 1) {
#pragma unroll
        for (int e = 0; e < NE; e++) {
            pg[e] += __shfl_xor_sync(0xffffffffu, pg[e], off);
            pc[e] += __shfl_xor_sync(0xffffffffu, pc[e], off);
        }
    }
    if (lane == 0) {
#pragma unroll
        for (int e = 0; e < NE; e++) { ws[wid][e] = pg[e]; ws[wid][NE + e] = pc[e]; }
    }
    __syncthreads();
    if (tid == 0 && writeLbl) {
        float sums[2 * NE];
#pragma unroll
        for (int j = 0; j < 2 * NE; j++) {
            float s = 0.f;
            for (int w = 0; w < 32; w++) s += ws[w][j];
            sums[j] = s;
        }
        float l = 0.f;
        for (int e = 0; e < NE; e++)
            l += (sums[e] / (float)NTOK) * (sums[NE + e] / (float)NTOK);
        out[(size_t)NTOK * DIM] = l * (float)NE;
    }
}

// ---------------- capacity dispatch: warp-ballot FCFS scan ----------------
__global__ void scan_k(const int* __restrict__ tokE, const float* __restrict__ tokG,
                       int* __restrict__ slotTok, float* __restrict__ slotGate)
{
    const int e = blockIdx.x, tid = threadIdx.x;   // 1024 threads = 32 warps
    const int lane = tid & 31, wid = tid >> 5;
    __shared__ int wsum[32];
    __shared__ int wbase[32];
    __shared__ int blksum;

    for (int c = tid; c < CAP; c += 1024) {
        slotTok[e * CAP + c]  = NTOK;
        slotGate[e * CAP + c] = 0.f;
    }
    __syncthreads();

    int base = 0;
    for (int tile = 0; tile < NTOK; tile += 1024) {
        int t  = tile + tid;
        int e0 = tokE[2 * t], e1 = tokE[2 * t + 1];
        int flag = (e0 == e) || (e1 == e);
        uint32_t b = __ballot_sync(0xffffffffu, flag);
        int lpre = __popc(b & ((1u << lane) - 1));
        if (lane == 0) wsum[wid] = __popc(b);
        __syncthreads();
        if (wid == 0) {
            int v = wsum[lane];
            int inc = v;
#pragma unroll
            for (int off = 1; off < 32; off <<= 1) {
                int y = __shfl_up_sync(0xffffffffu, inc, off);
                if (lane >= off) inc += y;
            }
            wbase[lane] = inc - v;
            if (lane == 31) blksum = inc;
        }
        __syncthreads();
        int pos = base + wbase[wid] + lpre;
        if (flag && pos < CAP) {
            slotTok[e * CAP + pos]  = t;
            slotGate[e * CAP + pos] = (e0 == e) ? tokG[2 * t] : tokG[2 * t + 1];
        }
        base += blksum;
        __syncthreads();
    }
}

// ---------------- host ----------------
extern "C" void kernel_launch(void* const* d_in, const int* in_sizes, int n_in,
                              void* d_out, int out_size)
{
    const float* x   = (const float*)d_in[0];
    const float* noi = (const float*)d_in[1];
    const float* Wr  = (const float*)d_in[2];
    const float* br  = (const float*)d_in[3];
    const float* Wn  = (const float*)d_in[4];
    const float* bn  = (const float*)d_in[5];
    const float* W1  = (const float*)d_in[6];
    const float* b1  = (const float*)d_in[7];
    const float* W2  = (const float*)d_in[8];
    const float* b2  = (const float*)d_in[9];
    const float* Ws1 = (const float*)d_in[10];
    const float* bs1 = (const float*)d_in[11];
    const float* Ws2 = (const float*)d_in[12];
    const float* bs2 = (const float*)d_in[13];
    float* out = (float*)d_out;

    __half *xf, *hsf, *hef;
    __half *w1th, *w1tl, *w2th, *w2tl, *ws1th, *ws1tl, *ws2th, *ws2tl;
    int *tokE, *slotTok; float *tokG, *slotGate;
    cudaGetSymbolAddress((void**)&xf, g_xf);
    cudaGetSymbolAddress((void**)&hsf, g_hsf);
    cudaGetSymbolAddress((void**)&hef, g_hef);
    cudaGetSymbolAddress((void**)&w1th, g_w1th); cudaGetSymbolAddress((void**)&w1tl, g_w1tl);
    cudaGetSymbolAddress((void**)&w2th, g_w2th); cudaGetSymbolAddress((void**)&w2tl, g_w2tl);
    cudaGetSymbolAddress((void**)&ws1th, g_ws1th); cudaGetSymbolAddress((void**)&ws1tl, g_ws1tl);
    cudaGetSymbolAddress((void**)&ws2th, g_ws2th); cudaGetSymbolAddress((void**)&ws2tl, g_ws2tl);
    cudaGetSymbolAddress((void**)&tokE, g_tokE); cudaGetSymbolAddress((void**)&tokG, g_tokG);
    cudaGetSymbolAddress((void**)&slotTok, g_slotTok); cudaGetSymbolAddress((void**)&slotGate, g_slotGate);

    cudaFuncSetAttribute(moe_gemm<0,0>, cudaFuncAttributeMaxDynamicSharedMemorySize, SMEM_BYTES);
    cudaFuncSetAttribute(moe_gemm<0,1>, cudaFuncAttributeMaxDynamicSharedMemorySize, SMEM_BYTES);
    cudaFuncSetAttribute(moe_gemm<1,0>, cudaFuncAttributeMaxDynamicSharedMemorySize, SMEM_BYTES);
    cudaFuncSetAttribute(moe_gemm<2,2>, cudaFuncAttributeMaxDynamicSharedMemorySize, SMEM_BYTES);

    dim3 tb(32, 8);
    dim3 gS(DIM / 128, NTOK / 128, 1);              // 8 x 64
    dim3 gE(DIM / 128, (CAP + 127) / 128, NE);      // 8 x 21 x 7

    // launches 0-4: prep (so ncu -s 5 captures the first GEMM)
    prep_x_k<<<NTOK * DIM / (256 * 4), 256>>>(x, xf);                 // 0
    prep_w_k<<<dim3(32, 32, 1),  tb>>>(Ws1, ws1th, ws1tl);            // 1
    prep_w_k<<<dim3(32, 32, 1),  tb>>>(Ws2, ws2th, ws2tl);            // 2
    prep_w_k<<<dim3(32, 32, NE), tb>>>(W1, w1th, w1tl);               // 3
    prep_w_k<<<dim3(32, 32, NE), tb>>>(W2, w2th, w2tl);               // 4

    // 5: shared expert layer 1 (profiled launch)
    moe_gemm<0,0><<<gS, 256, SMEM_BYTES>>>(xf, ws1th, ws1tl, bs1, nullptr, hsf,
                                           NTOK, nullptr, nullptr);

    // router / dispatch
    router_k<<<1024, 256>>>(x, noi, Wr, br, Wn, bn, tokE, tokG);      // 6
    lbl_k<<<1, 1024>>>(tokE, tokG, out, (out_size > NTOK * DIM) ? 1 : 0); // 7
    scan_k<<<NE, 1024>>>(tokE, tokG, slotTok, slotGate);              // 8

    // remaining GEMMs
    moe_gemm<0,1><<<gS, 256, SMEM_BYTES>>>(hsf, ws2th, ws2tl, bs2, out, nullptr,
                                           NTOK, nullptr, nullptr);   // 9
    moe_gemm<1,0><<<gE, 256, SMEM_BYTES>>>(xf, w1th, w1tl, b1, nullptr, hef,
                                           CAP, slotTok, nullptr);    // 10
    moe_gemm<2,2><<<gE, 256, SMEM_BYTES>>>(hef, w2th, w2tl, b2, out, nullptr,
                                           CAP, slotTok, slotGate);   // 11
    (void)in_sizes; (void)n_in;
}

// round 7
// speedup vs baseline: 3.3707x; 1.1544x over previous
#include <cuda_runtime.h>
#include <cuda_fp16.h>
#include <math.h>
#include <stdint.h>

// ---------------- static problem shape ----------------
#define NTOK 8192
#define DIM  1024
#define NE   7
#define CAP  2574            // int(NTOK*2/7*1.1)

// ---------------- scratch (device globals) ----------------
__device__ __half g_xf [NTOK * DIM];          // x rounded to fp16
__device__ __half g_hsf[NTOK * DIM];          // shared hidden fp16
__device__ __half g_hef[NE * CAP * DIM];      // expert hidden fp16
__device__ __half g_w1t[NE * DIM * DIM];      // W1^T fp16  [e][n][k]
__device__ __half g_w2t[NE * DIM * DIM];
__device__ __half g_ws1t[DIM * DIM];
__device__ __half g_ws2t[DIM * DIM];
__device__ int   g_tokE[NTOK * 2];
__device__ float g_tokG[NTOK * 2];
__device__ int   g_slotTok[NE * CAP];
__device__ float g_slotGate[NE * CAP];

// ---------------- PTX helpers (baseline ISA only) ----------------
__device__ __forceinline__ uint32_t smem_u32(const void* p) {
    uint32_t a;
    asm("{ .reg .u64 t; cvta.to.shared.u64 t, %1; cvt.u32.u64 %0, t; }" : "=r"(a) : "l"(p));
    return a;
}
#define SW64(x) ((x) ^ (((x) >> 3) & 0x30))
#define CP16(dst, src) asm volatile("cp.async.cg.shared.global [%0], [%1], 16;" :: "r"(dst), "l"(src))
#define CP_COMMIT() asm volatile("cp.async.commit_group;" ::: "memory")
#define CP_WAIT(n)  asm volatile("cp.async.wait_group %0;" :: "n"(n) : "memory")

#define LDSM4(R, a) \
    asm volatile("ldmatrix.sync.aligned.m8n8.x4.shared.b16 {%0,%1,%2,%3}, [%4];" \
        : "=r"((R)[0]), "=r"((R)[1]), "=r"((R)[2]), "=r"((R)[3]) : "r"(a))

#define MMA(C, A, B0, B1) \
    asm volatile("mma.sync.aligned.m16n8k16.row.col.f32.f16.f16.f32 " \
        "{%0,%1,%2,%3}, {%4,%5,%6,%7}, {%8,%9}, {%0,%1,%2,%3};" \
        : "+f"((C)[0]), "+f"((C)[1]), "+f"((C)[2]), "+f"((C)[3]) \
        : "r"((A)[0]), "r"((A)[1]), "r"((A)[2]), "r"((A)[3]), "r"(B0), "r"(B1))

// ---------------- smem: 6 stages x 16KB: A 8K | B 8K ----------------
#define STG_BYTES 16384u
#define NSTAGE    6
#define SMEM_BYTES (NSTAGE * 16384)
#define NCHUNK    (DIM / 32)
#define PF_DIST   5

// ---------------- GEMM: 128x128 CTA tile, BK=32, mma.sync fp16 ----------------
// AMODE: 0 = direct rows of Af, 1 = gather x rows via slotTok, 2 = expert-local hidden rows
// EPI:   0 = relu + fp16 store Oh, 1 = fp32 store OutF, 2 = gate*atomicAdd OutF
template <int AMODE, int EPI>
__global__ __launch_bounds__(256, 2)
void moe_gemm(const __half* __restrict__ Af, const __half* __restrict__ Bt,
              const float* __restrict__ bias, float* __restrict__ OutF,
              __half* __restrict__ Oh,
              int M, const int* __restrict__ slotTok, const float* __restrict__ slotGate)
{
    extern __shared__ char smem[];
    const int tid  = threadIdx.x;
    const int wid  = tid >> 5;
    const int lane = tid & 31;
    const int e    = blockIdx.z;
    const int m0   = blockIdx.y * 128;
    const int n0   = blockIdx.x * 128;
    const uint32_t sb = smem_u32(smem);

    const float* biasE = bias + e * DIM;

    // ---- per-thread global source rows for the fill ----
    const int rA = tid & 127;
    size_t aRowG;
    if (AMODE == 0) {
        aRowG = (size_t)(m0 + rA);
    } else if (AMODE == 1) {
        int slot = m0 + rA;
        int tok  = (slot < CAP) ? __ldg(&slotTok[e * CAP + slot]) : NTOK;
        if (tok >= NTOK) tok = 0;
        aRowG = (size_t)tok;
    } else {
        int r = m0 + rA; if (r > CAP - 1) r = CAP - 1;
        aRowG = (size_t)e * CAP + r;
    }
    const __half* src = (tid < 128)
        ? (Af + aRowG * DIM)
        : (Bt + ((size_t)e << 20) + (size_t)(n0 + rA) * DIM);
    const uint32_t dstBase = (tid < 128) ? 0u : 8192u;
    const uint32_t rowOff  = (uint32_t)rA * 64u;

    auto fill = [&](int c) {
        uint32_t stg = sb + (uint32_t)(c % NSTAGE) * STG_BYTES + dstBase;
        const __half* s = src + c * 32;
#pragma unroll
        for (int q = 0; q < 4; q++)
            CP16(stg + SW64(rowOff + q * 16u), s + q * 8);
        CP_COMMIT();
    };

    // ---- warp tiling: 2 (m) x 4 (n); warp tile 64x32 ----
    const int wm = (wid & 1) * 64;
    const int wn = (wid >> 1) * 32;

    const uint32_t aRowL = (uint32_t)(wm + ((lane >> 3) & 1) * 8 + (lane & 7));
    const uint32_t aOffL = (uint32_t)((lane >> 4) * 16);
    const uint32_t bRowL = (uint32_t)(wn + ((lane >> 4) & 1) * 8 + (lane & 7));
    const uint32_t bOffL = (uint32_t)(((lane >> 3) & 1) * 16);

    float acc[4][4][4];
#pragma unroll
    for (int i = 0; i < 4; i++)
#pragma unroll
        for (int j = 0; j < 4; j++)
#pragma unroll
            for (int q = 0; q < 4; q++) acc[i][j][q] = 0.f;

    fill(0); fill(1); fill(2); fill(3); fill(4);
#pragma unroll 1
    for (int c = 0; c < NCHUNK; c++) {
        int rem = NCHUNK - 1 - c;               // fills that may stay in flight
        if (rem >= 4)      { CP_WAIT(4); }
        else if (rem == 3) { CP_WAIT(3); }
        else if (rem == 2) { CP_WAIT(2); }
        else if (rem == 1) { CP_WAIT(1); }
        else               { CP_WAIT(0); }
        __syncthreads();
        if (c + PF_DIST < NCHUNK) fill(c + PF_DIST);

        uint32_t stg = sb + (uint32_t)(c % NSTAGE) * STG_BYTES;
#pragma unroll
        for (int ks = 0; ks < 2; ks++) {
            uint32_t bf[4][2];
#pragma unroll
            for (int bt = 0; bt < 2; bt++) {
                uint32_t r4[4];
                uint32_t boff = SW64((bRowL + bt * 16u) * 64u + bOffL + ks * 32u);
                LDSM4(r4, stg + 8192u + boff);
                bf[bt * 2][0] = r4[0]; bf[bt * 2][1] = r4[1];
                bf[bt * 2 + 1][0] = r4[2]; bf[bt * 2 + 1][1] = r4[3];
            }
#pragma unroll
            for (int mt = 0; mt < 4; mt++) {
                uint32_t a4[4];
                uint32_t aoff = SW64((aRowL + mt * 16u) * 64u + aOffL + ks * 32u);
                LDSM4(a4, stg + aoff);
#pragma unroll
                for (int nt = 0; nt < 4; nt++) MMA(acc[mt][nt], a4, bf[nt][0], bf[nt][1]);
            }
        }
    }

    // ---- epilogue ----
#pragma unroll
    for (int mt = 0; mt < 4; mt++) {
#pragma unroll
        for (int h = 0; h < 2; h++) {
            int rloc = wm + mt * 16 + (lane >> 2) + h * 8;
            int grow = m0 + rloc;

            bool   valid = true;
            size_t obase = 0;
            float  gate  = 0.f;
            if (EPI == 0) {
                if (AMODE == 0) {
                    obase = (size_t)grow * DIM;
                    valid = (grow < M);
                } else {
                    valid = (grow < CAP);
                    obase = ((size_t)e * CAP + (valid ? grow : 0)) * DIM;
                }
            } else if (EPI == 1) {
                valid = (grow < M);
                obase = (size_t)grow * DIM;
            } else {
                valid = false;
                if (grow < CAP) {
                    int tok = __ldg(&slotTok[e * CAP + grow]);
                    if (tok < NTOK) {
                        gate  = __ldg(&slotGate[e * CAP + grow]);
                        obase = (size_t)tok * DIM;
                        valid = true;
                    }
                }
            }
            if (!valid) continue;

#pragma unroll
            for (int nt = 0; nt < 4; nt++) {
                int nc = n0 + wn + nt * 8 + (lane & 3) * 2;
                float v0 = acc[mt][nt][h * 2 + 0] + __ldg(&biasE[nc]);
                float v1 = acc[mt][nt][h * 2 + 1] + __ldg(&biasE[nc + 1]);
                if (EPI == 0) {
                    v0 = fmaxf(v0, 0.f); v1 = fmaxf(v1, 0.f);
                    __half h0 = __float2half_rn(v0);
                    __half h1 = __float2half_rn(v1);
                    uint32_t hp = (uint32_t)*(ushort*)&h0 | ((uint32_t)*(ushort*)&h1 << 16);
                    *reinterpret_cast<uint32_t*>(Oh + obase + nc) = hp;
                } else if (EPI == 1) {
                    float2 v = make_float2(v0, v1);
                    *reinterpret_cast<float2*>(OutF + obase + nc) = v;
                } else {
                    atomicAdd(OutF + obase + nc,     gate * v0);
                    atomicAdd(OutF + obase + nc + 1, gate * v1);
                }
            }
        }
    }
}

// ---------------- prep: round x to fp16 ----------------
__global__ void prep_x_k(const float* __restrict__ x, __half* __restrict__ xf)
{
    int i = (blockIdx.x * blockDim.x + threadIdx.x) * 4;
    float4 v = *reinterpret_cast<const float4*>(x + i);
    __half h0 = __float2half_rn(v.x), h1 = __float2half_rn(v.y);
    __half h2 = __float2half_rn(v.z), h3 = __float2half_rn(v.w);
    ushort4 p = make_ushort4(*(ushort*)&h0, *(ushort*)&h1, *(ushort*)&h2, *(ushort*)&h3);
    *reinterpret_cast<ushort4*>(xf + i) = p;
}

// ---------------- prep: transpose + fp16 weights ----------------
__global__ void prep_w_k(const float* __restrict__ W, __half* __restrict__ Th)
{
    __shared__ float tile[32][33];
    const size_t mo = (size_t)blockIdx.z << 20;
    const float* Wm = W + mo;
    int n0 = blockIdx.x * 32, k0 = blockIdx.y * 32;
    for (int r = threadIdx.y; r < 32; r += 8)
        tile[r][threadIdx.x] = Wm[(size_t)(k0 + r) * DIM + n0 + threadIdx.x];
    __syncthreads();
    for (int r = threadIdx.y; r < 32; r += 8) {
        float v = tile[threadIdx.x][r];
        Th[mo + (size_t)(n0 + r) * DIM + k0 + threadIdx.x] = __float2half_rn(v);
    }
}

// ---------------- router ----------------
__global__ void router_k(const float* __restrict__ x, const float* __restrict__ noise,
                         const float* __restrict__ Wr, const float* __restrict__ br,
                         const float* __restrict__ Wn, const float* __restrict__ bn,
                         int* __restrict__ tokE, float* __restrict__ tokG)
{
    int gw   = (blockIdx.x * blockDim.x + threadIdx.x) >> 5;
    int lane = threadIdx.x & 31;
    if (gw >= NTOK) return;
    const float* xr = x + (size_t)gw * DIM;
    float aR[NE], aN[NE];
#pragma unroll
    for (int e = 0; e < NE; e++) { aR[e] = 0.f; aN[e] = 0.f; }
    for (int kk = 0; kk < DIM / 32; ++kk) {
        int   k  = kk * 32 + lane;
        float xv = xr[k];
        const float* wr = Wr + (size_t)k * NE;
        const float* wn = Wn + (size_t)k * NE;
#pragma unroll
        for (int e = 0; e < NE; e++) {
            aR[e] = fmaf(xv, __ldg(wr + e), aR[e]);
            aN[e] = fmaf(xv, __ldg(wn + e), aN[e]);
        }
    }
#pragma unroll
    for (int off = 16; off; off >>= 1) {
#pragma unroll
        for (int e = 0; e < NE; e++) {
            aR[e] += __shfl_xor_sync(0xffffffffu, aR[e], off);
            aN[e] += __shfl_xor_sync(0xffffffffu, aN[e], off);
        }
    }
    if (lane == 0) {
        float v1 = -1e30f, v2 = -1e30f; int i1 = 0, i2 = 0;
#pragma unroll
        for (int e = 0; e < NE; e++) {
            float ln = aN[e] + bn[e];
            float sp = fmaxf(ln, 0.f) + log1pf(expf(-fabsf(ln)));
            float v  = aR[e] + br[e] + noise[(size_t)gw * NE + e] * sp;
            if (v > v1)      { v2 = v1; i2 = i1; v1 = v; i1 = e; }
            else if (v > v2) { v2 = v;  i2 = e; }
        }
        float d = expf(v2 - v1);
        float inv = 1.f / (1.f + d);
        tokE[2 * gw] = i1; tokE[2 * gw + 1] = i2;
        tokG[2 * gw] = inv; tokG[2 * gw + 1] = d * inv;
    }
}

// ---------------- load-balance loss ----------------
__global__ void lbl_k(const int* __restrict__ tokE, const float* __restrict__ tokG,
                      float* __restrict__ out, int writeLbl)
{
    __shared__ float ws[32][2 * NE];
    int tid = threadIdx.x, lane = tid & 31, wid = tid >> 5;
    float pg[NE], pc[NE];
#pragma unroll
    for (int e = 0; e < NE; e++) { pg[e] = 0.f; pc[e] = 0.f; }
    for (int t = tid; t < NTOK; t += 1024) {
        int   e0 = tokE[2 * t], e1 = tokE[2 * t + 1];
        float g0 = tokG[2 * t], g1 = tokG[2 * t + 1];
#pragma unroll
        for (int e = 0; e < NE; e++) {
            pg[e] += (e0 == e ? g0 : 0.f) + (e1 == e ? g1 : 0.f);
            pc[e] += (e0 == e ? 1.f : 0.f) + (e1 == e ? 1.f : 0.f);
        }
    }
#pragma unroll
    for (int off = 16; off; off >>= 1) {
#pragma unroll
        for (int e = 0; e < NE; e++) {
            pg[e] += __shfl_xor_sync(0xffffffffu, pg[e], off);
            pc[e] += __shfl_xor_sync(0xffffffffu, pc[e], off);
        }
    }
    if (lane == 0) {
#pragma unroll
        for (int e = 0; e < NE; e++) { ws[wid][e] = pg[e]; ws[wid][NE + e] = pc[e]; }
    }
    __syncthreads();
    if (tid == 0 && writeLbl) {
        float sums[2 * NE];
#pragma unroll
        for (int j = 0; j < 2 * NE; j++) {
            float s = 0.f;
            for (int w = 0; w < 32; w++) s += ws[w][j];
            sums[j] = s;
        }
        float l = 0.f;
        for (int e = 0; e < NE; e++)
            l += (sums[e] / (float)NTOK) * (sums[NE + e] / (float)NTOK);
        out[(size_t)NTOK * DIM] = l * (float)NE;
    }
}

// ---------------- capacity dispatch: warp-ballot FCFS scan ----------------
__global__ void scan_k(const int* __restrict__ tokE, const float* __restrict__ tokG,
                       int* __restrict__ slotTok, float* __restrict__ slotGate)
{
    const int e = blockIdx.x, tid = threadIdx.x;   // 1024 threads = 32 warps
    const int lane = tid & 31, wid = tid >> 5;
    __shared__ int wsum[32];
    __shared__ int wbase[32];
    __shared__ int blksum;

    for (int c = tid; c < CAP; c += 1024) {
        slotTok[e * CAP + c]  = NTOK;
        slotGate[e * CAP + c] = 0.f;
    }
    __syncthreads();

    int base = 0;
    for (int tile = 0; tile < NTOK; tile += 1024) {
        int t  = tile + tid;
        int e0 = tokE[2 * t], e1 = tokE[2 * t + 1];
        int flag = (e0 == e) || (e1 == e);
        uint32_t b = __ballot_sync(0xffffffffu, flag);
        int lpre = __popc(b & ((1u << lane) - 1));
        if (lane == 0) wsum[wid] = __popc(b);
        __syncthreads();
        if (wid == 0) {
            int v = wsum[lane];
            int inc = v;
#pragma unroll
            for (int off = 1; off < 32; off <<= 1) {
                int y = __shfl_up_sync(0xffffffffu, inc, off);
                if (lane >= off) inc += y;
            }
            wbase[lane] = inc - v;
            if (lane == 31) blksum = inc;
        }
        __syncthreads();
        int pos = base + wbase[wid] + lpre;
        if (flag && pos < CAP) {
            slotTok[e * CAP + pos]  = t;
            slotGate[e * CAP + pos] = (e0 == e) ? tokG[2 * t] : tokG[2 * t + 1];
        }
        base += blksum;
        __syncthreads();
    }
}

// ---------------- host ----------------
extern "C" void kernel_launch(void* const* d_in, const int* in_sizes, int n_in,
                              void* d_out, int out_size)
{
    const float* x   = (const float*)d_in[0];
    const float* noi = (const float*)d_in[1];
    const float* Wr  = (const float*)d_in[2];
    const float* br  = (const float*)d_in[3];
    const float* Wn  = (const float*)d_in[4];
    const float* bn  = (const float*)d_in[5];
    const float* W1  = (const float*)d_in[6];
    const float* b1  = (const float*)d_in[7];
    const float* W2  = (const float*)d_in[8];
    const float* b2  = (const float*)d_in[9];
    const float* Ws1 = (const float*)d_in[10];
    const float* bs1 = (const float*)d_in[11];
    const float* Ws2 = (const float*)d_in[12];
    const float* bs2 = (const float*)d_in[13];
    float* out = (float*)d_out;

    __half *xf, *hsf, *hef, *w1t, *w2t, *ws1t, *ws2t;
    int *tokE, *slotTok; float *tokG, *slotGate;
    cudaGetSymbolAddress((void**)&xf, g_xf);
    cudaGetSymbolAddress((void**)&hsf, g_hsf);
    cudaGetSymbolAddress((void**)&hef, g_hef);
    cudaGetSymbolAddress((void**)&w1t, g_w1t);
    cudaGetSymbolAddress((void**)&w2t, g_w2t);
    cudaGetSymbolAddress((void**)&ws1t, g_ws1t);
    cudaGetSymbolAddress((void**)&ws2t, g_ws2t);
    cudaGetSymbolAddress((void**)&tokE, g_tokE); cudaGetSymbolAddress((void**)&tokG, g_tokG);
    cudaGetSymbolAddress((void**)&slotTok, g_slotTok); cudaGetSymbolAddress((void**)&slotGate, g_slotGate);

    cudaFuncSetAttribute(moe_gemm<0,0>, cudaFuncAttributeMaxDynamicSharedMemorySize, SMEM_BYTES);
    cudaFuncSetAttribute(moe_gemm<0,1>, cudaFuncAttributeMaxDynamicSharedMemorySize, SMEM_BYTES);
    cudaFuncSetAttribute(moe_gemm<1,0>, cudaFuncAttributeMaxDynamicSharedMemorySize, SMEM_BYTES);
    cudaFuncSetAttribute(moe_gemm<2,2>, cudaFuncAttributeMaxDynamicSharedMemorySize, SMEM_BYTES);

    dim3 tb(32, 8);
    dim3 gS(DIM / 128, NTOK / 128, 1);              // 8 x 64
    dim3 gE(DIM / 128, (CAP + 127) / 128, NE);      // 8 x 21 x 7

    // launches 0-4: prep (so ncu -s 5 captures the first GEMM)
    prep_x_k<<<NTOK * DIM / (256 * 4), 256>>>(x, xf);                 // 0
    prep_w_k<<<dim3(32, 32, 1),  tb>>>(Ws1, ws1t);                    // 1
    prep_w_k<<<dim3(32, 32, 1),  tb>>>(Ws2, ws2t);                    // 2
    prep_w_k<<<dim3(32, 32, NE), tb>>>(W1, w1t);                      // 3
    prep_w_k<<<dim3(32, 32, NE), tb>>>(W2, w2t);                      // 4

    // 5: shared expert layer 1 (profiled launch)
    moe_gemm<0,0><<<gS, 256, SMEM_BYTES>>>(xf, ws1t, bs1, nullptr, hsf,
                                           NTOK, nullptr, nullptr);

    // router / dispatch
    router_k<<<1024, 256>>>(x, noi, Wr, br, Wn, bn, tokE, tokG);      // 6
    lbl_k<<<1, 1024>>>(tokE, tokG, out, (out_size > NTOK * DIM) ? 1 : 0); // 7
    scan_k<<<NE, 1024>>>(tokE, tokG, slotTok, slotGate);              // 8

    // remaining GEMMs
    moe_gemm<0,1><<<gS, 256, SMEM_BYTES>>>(hsf, ws2t, bs2, out, nullptr,
                                           NTOK, nullptr, nullptr);   // 9
    moe_gemm<1,0><<<gE, 256, SMEM_BYTES>>>(xf, w1t, b1, nullptr, hef,
                                           CAP, slotTok, nullptr);    // 10
    moe_gemm<2,2><<<gE, 256, SMEM_BYTES>>>(hef, w2t, b2, out, nullptr,
                                           CAP, slotTok, slotGate);   // 11
    (void)in_sizes; (void)n_in;
}

// round 8
// speedup vs baseline: 3.4840x; 1.0336x over previous
#include <cuda_runtime.h>
#include <cuda_fp16.h>
#include <math.h>
#include <stdint.h>

// ---------------- static problem shape ----------------
#define NTOK 8192
#define DIM  1024
#define NE   7
#define CAP  2574            // int(NTOK*2/7*1.1)

// ---------------- scratch (device globals) ----------------
__device__ __half g_xf [NTOK * DIM];          // x rounded to fp16
__device__ __half g_hsf[NTOK * DIM];          // shared hidden fp16
__device__ __half g_hef[NE * CAP * DIM];      // expert hidden fp16
__device__ float  g_eout[NE * CAP * DIM];     // gated expert output fp32
__device__ __half g_w1t[NE * DIM * DIM];      // W1^T fp16  [e][n][k]
__device__ __half g_w2t[NE * DIM * DIM];
__device__ __half g_ws1t[DIM * DIM];
__device__ __half g_ws2t[DIM * DIM];
__device__ int   g_tokE[NTOK * 2];
__device__ float g_tokG[NTOK * 2];
__device__ int   g_slotTok[NE * CAP];
__device__ float g_slotGate[NE * CAP];
__device__ int   g_tokSlot[NTOK * 2];         // token -> global slot id (-1 = dropped)

// ---------------- PTX helpers (baseline ISA only) ----------------
__device__ __forceinline__ uint32_t smem_u32(const void* p) {
    uint32_t a;
    asm("{ .reg .u64 t; cvta.to.shared.u64 t, %1; cvt.u32.u64 %0, t; }" : "=r"(a) : "l"(p));
    return a;
}
#define SW128(x) ((x) ^ (((x) >> 3) & 0x70))
#define CP16(dst, src) asm volatile("cp.async.cg.shared.global [%0], [%1], 16;" :: "r"(dst), "l"(src))
#define CP_COMMIT() asm volatile("cp.async.commit_group;" ::: "memory")
#define CP_WAIT(n)  asm volatile("cp.async.wait_group %0;" :: "n"(n) : "memory")

#define LDSM4(R, a) \
    asm volatile("ldmatrix.sync.aligned.m8n8.x4.shared.b16 {%0,%1,%2,%3}, [%4];" \
        : "=r"((R)[0]), "=r"((R)[1]), "=r"((R)[2]), "=r"((R)[3]) : "r"(a))

#define MMA(C, A, B0, B1) \
    asm volatile("mma.sync.aligned.m16n8k16.row.col.f32.f16.f16.f32 " \
        "{%0,%1,%2,%3}, {%4,%5,%6,%7}, {%8,%9}, {%0,%1,%2,%3};" \
        : "+f"((C)[0]), "+f"((C)[1]), "+f"((C)[2]), "+f"((C)[3]) \
        : "r"((A)[0]), "r"((A)[1]), "r"((A)[2]), "r"((A)[3]), "r"(B0), "r"(B1))

// ---------------- smem: 3 stages x 32KB: A 16K | B 16K (128B rows, SW128) ----------------
#define STG_BYTES 32768u
#define NSTAGE    3
#define SMEM_BYTES (NSTAGE * 32768)
#define NCHUNK    (DIM / 64)
#define PF_DIST   2

// ---------------- GEMM: 128x128 CTA tile, BK=64, mma.sync fp16 ----------------
// AMODE: 0 = direct rows of Af, 1 = gather x rows via slotTok, 2 = expert-local hidden rows
// EPI:   0 = relu + fp16 store Oh, 1 = fp32 store OutF, 3 = gate*(v+b) store to eout (OutF)
template <int AMODE, int EPI>
__global__ __launch_bounds__(256, 2)
void moe_gemm(const __half* __restrict__ Af, const __half* __restrict__ Bt,
              const float* __restrict__ bias, float* __restrict__ OutF,
              __half* __restrict__ Oh,
              int M, const int* __restrict__ slotTok, const float* __restrict__ slotGate)
{
    extern __shared__ char smem[];
    const int tid  = threadIdx.x;
    const int wid  = tid >> 5;
    const int lane = tid & 31;
    const int e    = blockIdx.z;
    const int m0   = blockIdx.y * 128;
    const int n0   = blockIdx.x * 128;
    const uint32_t sb = smem_u32(smem);

    const float* biasE = bias + e * DIM;

    // ---- per-thread global source rows for the fill ----
    const int rA = tid & 127;
    size_t aRowG;
    if (AMODE == 0) {
        aRowG = (size_t)(m0 + rA);
    } else if (AMODE == 1) {
        int slot = m0 + rA;
        int tok  = (slot < CAP) ? __ldg(&slotTok[e * CAP + slot]) : NTOK;
        if (tok >= NTOK) tok = 0;
        aRowG = (size_t)tok;
    } else {
        int r = m0 + rA; if (r > CAP - 1) r = CAP - 1;
        aRowG = (size_t)e * CAP + r;
    }
    const __half* src = (tid < 128)
        ? (Af + aRowG * DIM)
        : (Bt + ((size_t)e << 20) + (size_t)(n0 + rA) * DIM);
    const uint32_t dstBase = (tid < 128) ? 0u : 16384u;
    const uint32_t rowOff  = (uint32_t)rA * 128u;

    auto fill = [&](int c) {
        uint32_t stg = sb + (uint32_t)(c % NSTAGE) * STG_BYTES + dstBase;
        const __half* s = src + c * 64;
#pragma unroll
        for (int q = 0; q < 8; q++)
            CP16(stg + SW128(rowOff + q * 16u), s + q * 8);
        CP_COMMIT();
    };

    // ---- warp tiling: 2 (m) x 4 (n); warp tile 64x32 ----
    const int wm = (wid & 1) * 64;
    const int wn = (wid >> 1) * 32;

    const uint32_t aRowL = (uint32_t)(wm + ((lane >> 3) & 1) * 8 + (lane & 7));
    const uint32_t aOffL = (uint32_t)((lane >> 4) * 16);
    const uint32_t bRowL = (uint32_t)(wn + ((lane >> 4) & 1) * 8 + (lane & 7));
    const uint32_t bOffL = (uint32_t)(((lane >> 3) & 1) * 16);

    float acc[4][4][4];
#pragma unroll
    for (int i = 0; i < 4; i++)
#pragma unroll
        for (int j = 0; j < 4; j++)
#pragma unroll
            for (int q = 0; q < 4; q++) acc[i][j][q] = 0.f;

    fill(0); fill(1);
#pragma unroll 1
    for (int c = 0; c < NCHUNK; c++) {
        if (c < NCHUNK - 1) { CP_WAIT(1); } else { CP_WAIT(0); }
        __syncthreads();
        if (c + PF_DIST < NCHUNK) fill(c + PF_DIST);

        uint32_t stg = sb + (uint32_t)(c % NSTAGE) * STG_BYTES;
#pragma unroll
        for (int ks = 0; ks < 4; ks++) {
            uint32_t bf[4][2];
#pragma unroll
            for (int bt = 0; bt < 2; bt++) {
                uint32_t r4[4];
                uint32_t boff = SW128((bRowL + bt * 16u) * 128u + bOffL + ks * 32u);
                LDSM4(r4, stg + 16384u + boff);
                bf[bt * 2][0] = r4[0]; bf[bt * 2][1] = r4[1];
                bf[bt * 2 + 1][0] = r4[2]; bf[bt * 2 + 1][1] = r4[3];
            }
#pragma unroll
            for (int mt = 0; mt < 4; mt++) {
                uint32_t a4[4];
                uint32_t aoff = SW128((aRowL + mt * 16u) * 128u + aOffL + ks * 32u);
                LDSM4(a4, stg + aoff);
#pragma unroll
                for (int nt = 0; nt < 4; nt++) MMA(acc[mt][nt], a4, bf[nt][0], bf[nt][1]);
            }
        }
    }

    // ---- epilogue ----
#pragma unroll
    for (int mt = 0; mt < 4; mt++) {
#pragma unroll
        for (int h = 0; h < 2; h++) {
            int rloc = wm + mt * 16 + (lane >> 2) + h * 8;
            int grow = m0 + rloc;

            bool   valid = true;
            size_t obase = 0;
            float  gate  = 0.f;
            if (EPI == 0) {
                if (AMODE == 0) {
                    obase = (size_t)grow * DIM;
                    valid = (grow < M);
                } else {
                    valid = (grow < CAP);
                    obase = ((size_t)e * CAP + (valid ? grow : 0)) * DIM;
                }
            } else if (EPI == 1) {
                valid = (grow < M);
                obase = (size_t)grow * DIM;
            } else {               // EPI == 3: gated store into eout
                valid = false;
                if (grow < CAP) {
                    int tok = __ldg(&slotTok[e * CAP + grow]);
                    if (tok < NTOK) {
                        gate  = __ldg(&slotGate[e * CAP + grow]);
                        obase = ((size_t)e * CAP + grow) * DIM;
                        valid = true;
                    }
                }
            }
            if (!valid) continue;

#pragma unroll
            for (int nt = 0; nt < 4; nt++) {
                int nc = n0 + wn + nt * 8 + (lane & 3) * 2;
                float v0 = acc[mt][nt][h * 2 + 0] + __ldg(&biasE[nc]);
                float v1 = acc[mt][nt][h * 2 + 1] + __ldg(&biasE[nc + 1]);
                if (EPI == 0) {
                    v0 = fmaxf(v0, 0.f); v1 = fmaxf(v1, 0.f);
                    __half h0 = __float2half_rn(v0);
                    __half h1 = __float2half_rn(v1);
                    uint32_t hp = (uint32_t)*(ushort*)&h0 | ((uint32_t)*(ushort*)&h1 << 16);
                    *reinterpret_cast<uint32_t*>(Oh + obase + nc) = hp;
                } else if (EPI == 1) {
                    *reinterpret_cast<float2*>(OutF + obase + nc) = make_float2(v0, v1);
                } else {
                    *reinterpret_cast<float2*>(OutF + obase + nc) =
                        make_float2(gate * v0, gate * v1);
                }
            }
        }
    }
}

// ---------------- prep: transpose + fp16 weights ----------------
__global__ void prep_w_k(const float* __restrict__ W, __half* __restrict__ Th)
{
    __shared__ float tile[32][33];
    const size_t mo = (size_t)blockIdx.z << 20;
    const float* Wm = W + mo;
    int n0 = blockIdx.x * 32, k0 = blockIdx.y * 32;
    for (int r = threadIdx.y; r < 32; r += 8)
        tile[r][threadIdx.x] = Wm[(size_t)(k0 + r) * DIM + n0 + threadIdx.x];
    __syncthreads();
    for (int r = threadIdx.y; r < 32; r += 8) {
        float v = tile[threadIdx.x][r];
        Th[mo + (size_t)(n0 + r) * DIM + k0 + threadIdx.x] = __float2half_rn(v);
    }
}

// ---------------- router (also produces fp16 x) ----------------
__global__ void router_k(const float* __restrict__ x, const float* __restrict__ noise,
                         const float* __restrict__ Wr, const float* __restrict__ br,
                         const float* __restrict__ Wn, const float* __restrict__ bn,
                         int* __restrict__ tokE, float* __restrict__ tokG,
                         __half* __restrict__ xf)
{
    int gw   = (blockIdx.x * blockDim.x + threadIdx.x) >> 5;
    int lane = threadIdx.x & 31;
    if (gw >= NTOK) return;
    const float* xr = x + (size_t)gw * DIM;
    __half*      xo = xf + (size_t)gw * DIM;
    float aR[NE], aN[NE];
#pragma unroll
    for (int e = 0; e < NE; e++) { aR[e] = 0.f; aN[e] = 0.f; }
    for (int kk = 0; kk < DIM / 32; ++kk) {
        int   k  = kk * 32 + lane;
        float xv = xr[k];
        xo[k] = __float2half_rn(xv);
        const float* wr = Wr + (size_t)k * NE;
        const float* wn = Wn + (size_t)k * NE;
#pragma unroll
        for (int e = 0; e < NE; e++) {
            aR[e] = fmaf(xv, __ldg(wr + e), aR[e]);
            aN[e] = fmaf(xv, __ldg(wn + e), aN[e]);
        }
    }
#pragma unroll
    for (int off = 16; off; off >>= 1) {
#pragma unroll
        for (int e = 0; e < NE; e++) {
            aR[e] += __shfl_xor_sync(0xffffffffu, aR[e], off);
            aN[e] += __shfl_xor_sync(0xffffffffu, aN[e], off);
        }
    }
    if (lane == 0) {
        float v1 = -1e30f, v2 = -1e30f; int i1 = 0, i2 = 0;
#pragma unroll
        for (int e = 0; e < NE; e++) {
            float ln = aN[e] + bn[e];
            float sp = fmaxf(ln, 0.f) + log1pf(expf(-fabsf(ln)));
            float v  = aR[e] + br[e] + noise[(size_t)gw * NE + e] * sp;
            if (v > v1)      { v2 = v1; i2 = i1; v1 = v; i1 = e; }
            else if (v > v2) { v2 = v;  i2 = e; }
        }
        float d = expf(v2 - v1);
        float inv = 1.f / (1.f + d);
        tokE[2 * gw] = i1; tokE[2 * gw + 1] = i2;
        tokG[2 * gw] = inv; tokG[2 * gw + 1] = d * inv;
    }
}

// ---------------- load-balance loss ----------------
__global__ void lbl_k(const int* __restrict__ tokE, const float* __restrict__ tokG,
                      float* __restrict__ out, int writeLbl)
{
    __shared__ float ws[32][2 * NE];
    int tid = threadIdx.x, lane = tid & 31, wid = tid >> 5;
    float pg[NE], pc[NE];
#pragma unroll
    for (int e = 0; e < NE; e++) { pg[e] = 0.f; pc[e] = 0.f; }
    for (int t = tid; t < NTOK; t += 1024) {
        int   e0 = tokE[2 * t], e1 = tokE[2 * t + 1];
        float g0 = tokG[2 * t], g1 = tokG[2 * t + 1];
#pragma unroll
        for (int e = 0; e < NE; e++) {
            pg[e] += (e0 == e ? g0 : 0.f) + (e1 == e ? g1 : 0.f);
            pc[e] += (e0 == e ? 1.f : 0.f) + (e1 == e ? 1.f : 0.f);
        }
    }
#pragma unroll
    for (int off = 16; off; off >>= 1) {
#pragma unroll
        for (int e = 0; e < NE; e++) {
            pg[e] += __shfl_xor_sync(0xffffffffu, pg[e], off);
            pc[e] += __shfl_xor_sync(0xffffffffu, pc[e], off);
        }
    }
    if (lane == 0) {
#pragma unroll
        for (int e = 0; e < NE; e++) { ws[wid][e] = pg[e]; ws[wid][NE + e] = pc[e]; }
    }
    __syncthreads();
    if (tid == 0 && writeLbl) {
        float sums[2 * NE];
#pragma unroll
        for (int j = 0; j < 2 * NE; j++) {
            float s = 0.f;
            for (int w = 0; w < 32; w++) s += ws[w][j];
            sums[j] = s;
        }
        float l = 0.f;
        for (int e = 0; e < NE; e++)
            l += (sums[e] / (float)NTOK) * (sums[NE + e] / (float)NTOK);
        out[(size_t)NTOK * DIM] = l * (float)NE;
    }
}

// ---------------- capacity dispatch: warp-ballot FCFS scan + token->slot map ----------------
__global__ void scan_k(const int* __restrict__ tokE, const float* __restrict__ tokG,
                       int* __restrict__ slotTok, float* __restrict__ slotGate,
                       int* __restrict__ tokSlot)
{
    const int e = blockIdx.x, tid = threadIdx.x;   // 1024 threads = 32 warps
    const int lane = tid & 31, wid = tid >> 5;
    __shared__ int wsum[32];
    __shared__ int wbase[32];
    __shared__ int blksum;

    for (int c = tid; c < CAP; c += 1024) {
        slotTok[e * CAP + c]  = NTOK;
        slotGate[e * CAP + c] = 0.f;
    }
    __syncthreads();

    int base = 0;
    for (int tile = 0; tile < NTOK; tile += 1024) {
        int t  = tile + tid;
        int e0 = tokE[2 * t], e1 = tokE[2 * t + 1];
        int flag = (e0 == e) || (e1 == e);
        uint32_t b = __ballot_sync(0xffffffffu, flag);
        int lpre = __popc(b & ((1u << lane) - 1));
        if (lane == 0) wsum[wid] = __popc(b);
        __syncthreads();
        if (wid == 0) {
            int v = wsum[lane];
            int inc = v;
#pragma unroll
            for (int off = 1; off < 32; off <<= 1) {
                int y = __shfl_up_sync(0xffffffffu, inc, off);
                if (lane >= off) inc += y;
            }
            wbase[lane] = inc - v;
            if (lane == 31) blksum = inc;
        }
        __syncthreads();
        int pos = base + wbase[wid] + lpre;
        if (flag) {
            int k = (e0 == e) ? 0 : 1;
            if (pos < CAP) {
                slotTok[e * CAP + pos]  = t;
                slotGate[e * CAP + pos] = (e0 == e) ? tokG[2 * t] : tokG[2 * t + 1];
                tokSlot[2 * t + k] = e * CAP + pos;
            } else {
                tokSlot[2 * t + k] = -1;
            }
        }
        base += blksum;
        __syncthreads();
    }
}

// ---------------- combine: out[t] += eout[slot0] + eout[slot1] ----------------
__global__ void combine_k(const int* __restrict__ tokSlot,
                          const float* __restrict__ eout, float* __restrict__ out)
{
    int t = blockIdx.x;
    int d = threadIdx.x * 4;
    int s0 = __ldg(&tokSlot[2 * t]);
    int s1 = __ldg(&tokSlot[2 * t + 1]);
    float4 v = *reinterpret_cast<float4*>(out + (size_t)t * DIM + d);
    if (s0 >= 0) {
        float4 a = *reinterpret_cast<const float4*>(eout + (size_t)s0 * DIM + d);
        v.x += a.x; v.y += a.y; v.z += a.z; v.w += a.w;
    }
    if (s1 >= 0) {
        float4 a = *reinterpret_cast<const float4*>(eout + (size_t)s1 * DIM + d);
        v.x += a.x; v.y += a.y; v.z += a.z; v.w += a.w;
    }
    *reinterpret_cast<float4*>(out + (size_t)t * DIM + d) = v;
}

// ---------------- host ----------------
extern "C" void kernel_launch(void* const* d_in, const int* in_sizes, int n_in,
                              void* d_out, int out_size)
{
    const float* x   = (const float*)d_in[0];
    const float* noi = (const float*)d_in[1];
    const float* Wr  = (const float*)d_in[2];
    const float* br  = (const float*)d_in[3];
    const float* Wn  = (const float*)d_in[4];
    const float* bn  = (const float*)d_in[5];
    const float* W1  = (const float*)d_in[6];
    const float* b1  = (const float*)d_in[7];
    const float* W2  = (const float*)d_in[8];
    const float* b2  = (const float*)d_in[9];
    const float* Ws1 = (const float*)d_in[10];
    const float* bs1 = (const float*)d_in[11];
    const float* Ws2 = (const float*)d_in[12];
    const float* bs2 = (const float*)d_in[13];
    float* out = (float*)d_out;

    __half *xf, *hsf, *hef, *w1t, *w2t, *ws1t, *ws2t;
    float *eout;
    int *tokE, *slotTok, *tokSlot; float *tokG, *slotGate;
    cudaGetSymbolAddress((void**)&xf, g_xf);
    cudaGetSymbolAddress((void**)&hsf, g_hsf);
    cudaGetSymbolAddress((void**)&hef, g_hef);
    cudaGetSymbolAddress((void**)&eout, g_eout);
    cudaGetSymbolAddress((void**)&w1t, g_w1t);
    cudaGetSymbolAddress((void**)&w2t, g_w2t);
    cudaGetSymbolAddress((void**)&ws1t, g_ws1t);
    cudaGetSymbolAddress((void**)&ws2t, g_ws2t);
    cudaGetSymbolAddress((void**)&tokE, g_tokE); cudaGetSymbolAddress((void**)&tokG, g_tokG);
    cudaGetSymbolAddress((void**)&slotTok, g_slotTok); cudaGetSymbolAddress((void**)&slotGate, g_slotGate);
    cudaGetSymbolAddress((void**)&tokSlot, g_tokSlot);

    cudaFuncSetAttribute(moe_gemm<0,0>, cudaFuncAttributeMaxDynamicSharedMemorySize, SMEM_BYTES);
    cudaFuncSetAttribute(moe_gemm<0,1>, cudaFuncAttributeMaxDynamicSharedMemorySize, SMEM_BYTES);
    cudaFuncSetAttribute(moe_gemm<1,0>, cudaFuncAttributeMaxDynamicSharedMemorySize, SMEM_BYTES);
    cudaFuncSetAttribute(moe_gemm<2,3>, cudaFuncAttributeMaxDynamicSharedMemorySize, SMEM_BYTES);

    dim3 tb(32, 8);
    dim3 gS(DIM / 128, NTOK / 128, 1);              // 8 x 64
    dim3 gE(DIM / 128, (CAP + 127) / 128, NE);      // 8 x 21 x 7

    // launches 0-4 (ncu -s 5 lands on the first GEMM)
    prep_w_k<<<dim3(32, 32, 1),  tb>>>(Ws1, ws1t);                    // 0
    prep_w_k<<<dim3(32, 32, 1),  tb>>>(Ws2, ws2t);                    // 1
    prep_w_k<<<dim3(32, 32, NE), tb>>>(W1, w1t);                      // 2
    prep_w_k<<<dim3(32, 32, NE), tb>>>(W2, w2t);                      // 3
    router_k<<<1024, 256>>>(x, noi, Wr, br, Wn, bn, tokE, tokG, xf);  // 4

    // 5: shared expert layer 1 (profiled launch)
    moe_gemm<0,0><<<gS, 256, SMEM_BYTES>>>(xf, ws1t, bs1, nullptr, hsf,
                                           NTOK, nullptr, nullptr);

    lbl_k<<<1, 1024>>>(tokE, tokG, out, (out_size > NTOK * DIM) ? 1 : 0); // 6
    scan_k<<<NE, 1024>>>(tokE, tokG, slotTok, slotGate, tokSlot);         // 7

    moe_gemm<0,1><<<gS, 256, SMEM_BYTES>>>(hsf, ws2t, bs2, out, nullptr,
                                           NTOK, nullptr, nullptr);   // 8
    moe_gemm<1,0><<<gE, 256, SMEM_BYTES>>>(xf, w1t, b1, nullptr, hef,
                                           CAP, slotTok, nullptr);    // 9
    moe_gemm<2,3><<<gE, 256, SMEM_BYTES>>>(hef, w2t, b2, eout, nullptr,
                                           CAP, slotTok, slotGate);   // 10
    combine_k<<<NTOK, 256>>>(tokSlot, eout, out);                     // 11
    (void)in_sizes; (void)n_in;
}

// round 12
// speedup vs baseline: 3.8354x; 1.1009x over previous
#include <cuda_runtime.h>
#include <cuda_fp16.h>
#include <math.h>
#include <stdint.h>

// ---------------- static problem shape ----------------
#define NTOK 8192
#define DIM  1024
#define NE   7
#define CAP  2574            // int(NTOK*2/7*1.1)
#define YEXP 21              // ceil(CAP/128)

// ---------------- scratch (device globals) ----------------
__device__ __half g_xf [NTOK * DIM];
__device__ __half g_hsf[NTOK * DIM];
__device__ __half g_hef[NE * CAP * DIM];
__device__ float  g_eout[NE * CAP * DIM];
__device__ __half g_w1t[NE * DIM * DIM];
__device__ __half g_w2t[NE * DIM * DIM];
__device__ __half g_ws1t[DIM * DIM];
__device__ __half g_ws2t[DIM * DIM];
__device__ int   g_tokE[NTOK * 2];
__device__ float g_tokG[NTOK * 2];
__device__ int   g_slotTok[NE * CAP];
__device__ float g_slotGate[NE * CAP];
__device__ int   g_tokSlot[NTOK * 2];

// ---------------- PTX helpers ----------------
__device__ __forceinline__ uint32_t smem_u32(const void* p) {
    uint32_t a;
    asm("{ .reg .u64 t; cvta.to.shared.u64 t, %1; cvt.u32.u64 %0, t; }" : "=r"(a) : "l"(p));
    return a;
}
#define SW128(x) ((x) ^ (((x) >> 3) & 0x70))
#define CP16(dst, src) asm volatile("cp.async.cg.shared.global [%0], [%1], 16;" :: "r"(dst), "l"(src))
#define CP_COMMIT() asm volatile("cp.async.commit_group;" ::: "memory")
#define CP_WAIT(n)  asm volatile("cp.async.wait_group %0;" :: "n"(n) : "memory")

#define LDSM4(R, a) \
    asm volatile("ldmatrix.sync.aligned.m8n8.x4.shared.b16 {%0,%1,%2,%3}, [%4];" \
        : "=r"((R)[0]), "=r"((R)[1]), "=r"((R)[2]), "=r"((R)[3]) : "r"(a))

#define MMA(C, A, B0, B1) \
    asm volatile("mma.sync.aligned.m16n8k16.row.col.f32.f16.f16.f32 " \
        "{%0,%1,%2,%3}, {%4,%5,%6,%7}, {%8,%9}, {%0,%1,%2,%3};" \
        : "+f"((C)[0]), "+f"((C)[1]), "+f"((C)[2]), "+f"((C)[3]) \
        : "r"((A)[0]), "r"((A)[1]), "r"((A)[2]), "r"((A)[3]), "r"(B0), "r"(B1))

// ---------------- smem: 3 stages x 32KB: A 16K | B 16K (128B rows, SW128) ----------------
#define STG_BYTES 32768u
#define NSTAGE    3
#define SMEM_BYTES (NSTAGE * 32768)
#define NCHUNK    (DIM / 64)
#define PF_DIST   2

// ---------------- merged GEMM: z=0..6 experts, z=7 shared ----------------
// PHASE 1: A=xf (expert: gather rows via slotTok; shared: direct); out = relu -> hef/hsf (fp16)
// PHASE 2: A=hef/hsf; expert: gate*(v+b) -> eout; shared: v+b -> out
template <int PHASE>
__global__ __launch_bounds__(256, 2)
void moe_gemm(const __half* __restrict__ Ae, const __half* __restrict__ As,
              const __half* __restrict__ Be, const __half* __restrict__ Bs,
              const float* __restrict__ biasE_, const float* __restrict__ biasS_,
              __half* __restrict__ OhE, __half* __restrict__ OhS,
              float* __restrict__ OfE, float* __restrict__ OfS,
              const int* __restrict__ slotTok, const float* __restrict__ slotGate)
{
    const int z = blockIdx.z;
    const bool sh = (z == NE);
    if (!sh && blockIdx.y >= YEXP) return;

    extern __shared__ char smem[];
    const int tid  = threadIdx.x;
    const int wid  = tid >> 5;
    const int lane = tid & 31;
    const int e    = sh ? 0 : z;
    const int m0   = blockIdx.y * 128;
    const int n0   = blockIdx.x * 128;
    const uint32_t sb = smem_u32(smem);

    const float* bias = sh ? biasS_ : (biasE_ + e * DIM);
    const __half* Bt  = sh ? Bs : (Be + ((size_t)e << 20));

    // ---- per-thread source rows for fill ----
    const int rA = tid & 127;
    const __half* src;
    if (tid < 128) {
        size_t aRowG;
        if (sh) {
            aRowG = (size_t)(m0 + rA);
            src = As + aRowG * DIM;
        } else if (PHASE == 1) {
            int slot = m0 + rA;
            int tok  = (slot < CAP) ? __ldg(&slotTok[e * CAP + slot]) : NTOK;
            if (tok >= NTOK) tok = 0;
            src = Ae + (size_t)tok * DIM;
        } else {
            int r = m0 + rA; if (r > CAP - 1) r = CAP - 1;
            src = Ae + ((size_t)e * CAP + r) * DIM;
        }
    } else {
        src = Bt + (size_t)(n0 + rA) * DIM;
    }
    const uint32_t dstBase = (tid < 128) ? 0u : 16384u;
    const uint32_t rowOff  = (uint32_t)rA * 128u;

    auto fill = [&](int c) {
        uint32_t stg = sb + (uint32_t)(c % NSTAGE) * STG_BYTES + dstBase;
        const __half* s = src + c * 64;
#pragma unroll
        for (int q = 0; q < 8; q++)
            CP16(stg + SW128(rowOff + q * 16u), s + q * 8);
        CP_COMMIT();
    };

    // ---- warp tiling: 2 (m) x 4 (n) ----
    const int wm = (wid & 1) * 64;
    const int wn = (wid >> 1) * 32;

    const uint32_t aRowL = (uint32_t)(wm + ((lane >> 3) & 1) * 8 + (lane & 7));
    const uint32_t aOffL = (uint32_t)((lane >> 4) * 16);
    const uint32_t bRowL = (uint32_t)(wn + ((lane >> 4) & 1) * 8 + (lane & 7));
    const uint32_t bOffL = (uint32_t)(((lane >> 3) & 1) * 16);

    float acc[4][4][4];
#pragma unroll
    for (int i = 0; i < 4; i++)
#pragma unroll
        for (int j = 0; j < 4; j++)
#pragma unroll
            for (int q = 0; q < 4; q++) acc[i][j][q] = 0.f;

    fill(0); fill(1);
#pragma unroll 1
    for (int c = 0; c < NCHUNK; c++) {
        if (c < NCHUNK - 1) { CP_WAIT(1); } else { CP_WAIT(0); }
        __syncthreads();
        if (c + PF_DIST < NCHUNK) fill(c + PF_DIST);

        uint32_t stg = sb + (uint32_t)(c % NSTAGE) * STG_BYTES;

        // register double-buffered software pipeline
        uint32_t bf[2][4][2];
        uint32_t areg[2][4];

        // prologue: B(ks=0) -> bf[0], A(ks=0,mt=0) -> areg[0]
#pragma unroll
        for (int bt = 0; bt < 2; bt++) {
            uint32_t r4[4];
            LDSM4(r4, stg + 16384u + SW128((bRowL + bt * 16u) * 128u + bOffL));
            bf[0][bt * 2][0] = r4[0]; bf[0][bt * 2][1] = r4[1];
            bf[0][bt * 2 + 1][0] = r4[2]; bf[0][bt * 2 + 1][1] = r4[3];
        }
        LDSM4(areg[0], stg + SW128(aRowL * 128u + aOffL));

#pragma unroll
        for (int ks = 0; ks < 4; ks++) {
            const int bcur = ks & 1, bnxt = bcur ^ 1;
#pragma unroll
            for (int mt = 0; mt < 4; mt++) {
                const int ap = (ks * 4 + mt) & 1, an = ap ^ 1;
                if (mt == 0 && ks < 3) {
#pragma unroll
                    for (int bt = 0; bt < 2; bt++) {
                        uint32_t r4[4];
                        LDSM4(r4, stg + 16384u +
                              SW128((bRowL + bt * 16u) * 128u + bOffL + (ks + 1) * 32u));
                        bf[bnxt][bt * 2][0] = r4[0]; bf[bnxt][bt * 2][1] = r4[1];
                        bf[bnxt][bt * 2 + 1][0] = r4[2]; bf[bnxt][bt * 2 + 1][1] = r4[3];
                    }
                }
                if (mt < 3)
                    LDSM4(areg[an], stg + SW128((aRowL + (mt + 1) * 16u) * 128u + aOffL + ks * 32u));
                else if (ks < 3)
                    LDSM4(areg[an], stg + SW128(aRowL * 128u + aOffL + (ks + 1) * 32u));
#pragma unroll
                for (int nt = 0; nt < 4; nt++)
                    MMA(acc[mt][nt], areg[ap], bf[bcur][nt][0], bf[bcur][nt][1]);
            }
        }
    }

    // ---- epilogue ----
#pragma unroll
    for (int mt = 0; mt < 4; mt++) {
#pragma unroll
        for (int h = 0; h < 2; h++) {
            int rloc = wm + mt * 16 + (lane >> 2) + h * 8;
            int grow = m0 + rloc;

            bool   valid = true;
            size_t obase = 0;
            float  gate  = 0.f;
            if (sh) {
                obase = (size_t)grow * DIM;          // grow < 8192 always
            } else if (PHASE == 1) {
                valid = (grow < CAP);
                obase = ((size_t)e * CAP + (valid ? grow : 0)) * DIM;
            } else {
                valid = false;
                if (grow < CAP) {
                    int tok = __ldg(&slotTok[e * CAP + grow]);
                    if (tok < NTOK) {
                        gate  = __ldg(&slotGate[e * CAP + grow]);
                        obase = ((size_t)e * CAP + grow) * DIM;
                        valid = true;
                    }
                }
            }
            if (!valid) continue;

#pragma unroll
            for (int nt = 0; nt < 4; nt++) {
                int nc = n0 + wn + nt * 8 + (lane & 3) * 2;
                float v0 = acc[mt][nt][h * 2 + 0] + __ldg(&bias[nc]);
                float v1 = acc[mt][nt][h * 2 + 1] + __ldg(&bias[nc + 1]);
                if (PHASE == 1) {
                    v0 = fmaxf(v0, 0.f); v1 = fmaxf(v1, 0.f);
                    __half h0 = __float2half_rn(v0);
                    __half h1 = __float2half_rn(v1);
                    uint32_t hp = (uint32_t)*(ushort*)&h0 | ((uint32_t)*(ushort*)&h1 << 16);
                    __half* O = sh ? OhS : OhE;
                    *reinterpret_cast<uint32_t*>(O + obase + nc) = hp;
                } else if (sh) {
                    *reinterpret_cast<float2*>(OfS + obase + nc) = make_float2(v0, v1);
                } else {
                    *reinterpret_cast<float2*>(OfE + obase + nc) =
                        make_float2(gate * v0, gate * v1);
                }
            }
        }
    }
}

// ---------------- prep: transpose + fp16 weights ----------------
__global__ void prep_w_k(const float* __restrict__ W, __half* __restrict__ Th)
{
    __shared__ float tile[32][33];
    const size_t mo = (size_t)blockIdx.z << 20;
    const float* Wm = W + mo;
    int n0 = blockIdx.x * 32, k0 = blockIdx.y * 32;
    for (int r = threadIdx.y; r < 32; r += 8)
        tile[r][threadIdx.x] = Wm[(size_t)(k0 + r) * DIM + n0 + threadIdx.x];
    __syncthreads();
    for (int r = threadIdx.y; r < 32; r += 8) {
        float v = tile[threadIdx.x][r];
        Th[mo + (size_t)(n0 + r) * DIM + k0 + threadIdx.x] = __float2half_rn(v);
    }
}

// ---------------- router (also produces fp16 x) ----------------
__global__ void router_k(const float* __restrict__ x, const float* __restrict__ noise,
                         const float* __restrict__ Wr, const float* __restrict__ br,
                         const float* __restrict__ Wn, const float* __restrict__ bn,
                         int* __restrict__ tokE, float* __restrict__ tokG,
                         __half* __restrict__ xf)
{
    int gw   = (blockIdx.x * blockDim.x + threadIdx.x) >> 5;
    int lane = threadIdx.x & 31;
    if (gw >= NTOK) return;
    const float* xr = x + (size_t)gw * DIM;
    __half*      xo = xf + (size_t)gw * DIM;
    float aR[NE], aN[NE];
#pragma unroll
    for (int e = 0; e < NE; e++) { aR[e] = 0.f; aN[e] = 0.f; }
    for (int kk = 0; kk < DIM / 32; ++kk) {
        int   k  = kk * 32 + lane;
        float xv = xr[k];
        xo[k] = __float2half_rn(xv);
        const float* wr = Wr + (size_t)k * NE;
        const float* wn = Wn + (size_t)k * NE;
#pragma unroll
        for (int e = 0; e < NE; e++) {
            aR[e] = fmaf(xv, __ldg(wr + e), aR[e]);
            aN[e] = fmaf(xv, __ldg(wn + e), aN[e]);
        }
    }
#pragma unroll
    for (int off = 16; off; off >>= 1) {
#pragma unroll
        for (int e = 0; e < NE; e++) {
            aR[e] += __shfl_xor_sync(0xffffffffu, aR[e], off);
            aN[e] += __shfl_xor_sync(0xffffffffu, aN[e], off);
        }
    }
    if (lane == 0) {
        float v1 = -1e30f, v2 = -1e30f; int i1 = 0, i2 = 0;
#pragma unroll
        for (int e = 0; e < NE; e++) {
            float ln = aN[e] + bn[e];
            float sp = fmaxf(ln, 0.f) + log1pf(expf(-fabsf(ln)));
            float v  = aR[e] + br[e] + noise[(size_t)gw * NE + e] * sp;
            if (v > v1)      { v2 = v1; i2 = i1; v1 = v; i1 = e; }
            else if (v > v2) { v2 = v;  i2 = e; }
        }
        float d = expf(v2 - v1);
        float inv = 1.f / (1.f + d);
        tokE[2 * gw] = i1; tokE[2 * gw + 1] = i2;
        tokG[2 * gw] = inv; tokG[2 * gw + 1] = d * inv;
    }
}

// ---------------- load-balance loss ----------------
__global__ void lbl_k(const int* __restrict__ tokE, const float* __restrict__ tokG,
                      float* __restrict__ out, int writeLbl)
{
    __shared__ float ws[32][2 * NE];
    int tid = threadIdx.x, lane = tid & 31, wid = tid >> 5;
    float pg[NE], pc[NE];
#pragma unroll
    for (int e = 0; e < NE; e++) { pg[e] = 0.f; pc[e] = 0.f; }
    for (int t = tid; t < NTOK; t += 1024) {
        int   e0 = tokE[2 * t], e1 = tokE[2 * t + 1];
        float g0 = tokG[2 * t], g1 = tokG[2 * t + 1];
#pragma unroll
        for (int e = 0; e < NE; e++) {
            pg[e] += (e0 == e ? g0 : 0.f) + (e1 == e ? g1 : 0.f);
            pc[e] += (e0 == e ? 1.f : 0.f) + (e1 == e ? 1.f : 0.f);
        }
    }
#pragma unroll
    for (int off = 16; off; off >>= 1) {
#pragma unroll
        for (int e = 0; e < NE; e++) {
            pg[e] += __shfl_xor_sync(0xffffffffu, pg[e], off);
            pc[e] += __shfl_xor_sync(0xffffffffu, pc[e], off);
        }
    }
    if (lane == 0) {
#pragma unroll
        for (int e = 0; e < NE; e++) { ws[wid][e] = pg[e]; ws[wid][NE + e] = pc[e]; }
    }
    __syncthreads();
    if (tid == 0 && writeLbl) {
        float sums[2 * NE];
#pragma unroll
        for (int j = 0; j < 2 * NE; j++) {
            float s = 0.f;
            for (int w = 0; w < 32; w++) s += ws[w][j];
            sums[j] = s;
        }
        float l = 0.f;
        for (int e = 0; e < NE; e++)
            l += (sums[e] / (float)NTOK) * (sums[NE + e] / (float)NTOK);
        out[(size_t)NTOK * DIM] = l * (float)NE;
    }
}

// ---------------- capacity dispatch ----------------
__global__ void scan_k(const int* __restrict__ tokE, const float* __restrict__ tokG,
                       int* __restrict__ slotTok, float* __restrict__ slotGate,
                       int* __restrict__ tokSlot)
{
    const int e = blockIdx.x, tid = threadIdx.x;
    const int lane = tid & 31, wid = tid >> 5;
    __shared__ int wsum[32];
    __shared__ int wbase[32];
    __shared__ int blksum;

    for (int c = tid; c < CAP; c += 1024) {
        slotTok[e * CAP + c]  = NTOK;
        slotGate[e * CAP + c] = 0.f;
    }
    __syncthreads();

    int base = 0;
    for (int tile = 0; tile < NTOK; tile += 1024) {
        int t  = tile + tid;
        int e0 = tokE[2 * t], e1 = tokE[2 * t + 1];
        int flag = (e0 == e) || (e1 == e);
        uint32_t b = __ballot_sync(0xffffffffu, flag);
        int lpre = __popc(b & ((1u << lane) - 1));
        if (lane == 0) wsum[wid] = __popc(b);
        __syncthreads();
        if (wid == 0) {
            int v = wsum[lane];
            int inc = v;
#pragma unroll
            for (int off = 1; off < 32; off <<= 1) {
                int y = __shfl_up_sync(0xffffffffu, inc, off);
                if (lane >= off) inc += y;
            }
            wbase[lane] = inc - v;
            if (lane == 31) blksum = inc;
        }
        __syncthreads();
        int pos = base + wbase[wid] + lpre;
        if (flag) {
            int k = (e0 == e) ? 0 : 1;
            if (pos < CAP) {
                slotTok[e * CAP + pos]  = t;
                slotGate[e * CAP + pos] = (e0 == e) ? tokG[2 * t] : tokG[2 * t + 1];
                tokSlot[2 * t + k] = e * CAP + pos;
            } else {
                tokSlot[2 * t + k] = -1;
            }
        }
        base += blksum;
        __syncthreads();
    }
}

// ---------------- combine ----------------
__global__ void combine_k(const int* __restrict__ tokSlot,
                          const float* __restrict__ eout, float* __restrict__ out)
{
    int t = blockIdx.x;
    int d = threadIdx.x * 4;
    int s0 = __ldg(&tokSlot[2 * t]);
    int s1 = __ldg(&tokSlot[2 * t + 1]);
    float4 v = *reinterpret_cast<float4*>(out + (size_t)t * DIM + d);
    if (s0 >= 0) {
        float4 a = *reinterpret_cast<const float4*>(eout + (size_t)s0 * DIM + d);
        v.x += a.x; v.y += a.y; v.z += a.z; v.w += a.w;
    }
    if (s1 >= 0) {
        float4 a = *reinterpret_cast<const float4*>(eout + (size_t)s1 * DIM + d);
        v.x += a.x; v.y += a.y; v.z += a.z; v.w += a.w;
    }
    *reinterpret_cast<float4*>(out + (size_t)t * DIM + d) = v;
}

// ---------------- host ----------------
extern "C" void kernel_launch(void* const* d_in, const int* in_sizes, int n_in,
                              void* d_out, int out_size)
{
    const float* x   = (const float*)d_in[0];
    const float* noi = (const float*)d_in[1];
    const float* Wr  = (const float*)d_in[2];
    const float* br  = (const float*)d_in[3];
    const float* Wn  = (const float*)d_in[4];
    const float* bn  = (const float*)d_in[5];
    const float* W1  = (const float*)d_in[6];
    const float* b1  = (const float*)d_in[7];
    const float* W2  = (const float*)d_in[8];
    const float* b2  = (const float*)d_in[9];
    const float* Ws1 = (const float*)d_in[10];
    const float* bs1 = (const float*)d_in[11];
    const float* Ws2 = (const float*)d_in[12];
    const float* bs2 = (const float*)d_in[13];
    float* out = (float*)d_out;

    __half *xf, *hsf, *hef, *w1t, *w2t, *ws1t, *ws2t;
    float *eout;
    int *tokE, *slotTok, *tokSlot; float *tokG, *slotGate;
    cudaGetSymbolAddress((void**)&xf, g_xf);
    cudaGetSymbolAddress((void**)&hsf, g_hsf);
    cudaGetSymbolAddress((void**)&hef, g_hef);
    cudaGetSymbolAddress((void**)&eout, g_eout);
    cudaGetSymbolAddress((void**)&w1t, g_w1t);
    cudaGetSymbolAddress((void**)&w2t, g_w2t);
    cudaGetSymbolAddress((void**)&ws1t, g_ws1t);
    cudaGetSymbolAddress((void**)&ws2t, g_ws2t);
    cudaGetSymbolAddress((void**)&tokE, g_tokE); cudaGetSymbolAddress((void**)&tokG, g_tokG);
    cudaGetSymbolAddress((void**)&slotTok, g_slotTok); cudaGetSymbolAddress((void**)&slotGate, g_slotGate);
    cudaGetSymbolAddress((void**)&tokSlot, g_tokSlot);

    cudaFuncSetAttribute(moe_gemm<1>, cudaFuncAttributeMaxDynamicSharedMemorySize, SMEM_BYTES);
    cudaFuncSetAttribute(moe_gemm<2>, cudaFuncAttributeMaxDynamicSharedMemorySize, SMEM_BYTES);

    dim3 tb(32, 8);
    dim3 gG(DIM / 128, NTOK / 128, NE + 1);   // 8 x 64 x 8 (z=7 shared, z<7 experts y<21)

    router_k<<<1024, 256>>>(x, noi, Wr, br, Wn, bn, tokE, tokG, xf);      // 0
    prep_w_k<<<dim3(32, 32, 1),  tb>>>(Ws1, ws1t);                        // 1
    prep_w_k<<<dim3(32, 32, NE), tb>>>(W1, w1t);                          // 2
    lbl_k<<<1, 1024>>>(tokE, tokG, out, (out_size > NTOK * DIM) ? 1 : 0); // 3
    scan_k<<<NE, 1024>>>(tokE, tokG, slotTok, slotGate, tokSlot);         // 4

    // 5: merged GEMM phase 1 (experts + shared)
    moe_gemm<1><<<gG, 256, SMEM_BYTES>>>(xf, xf, w1t, ws1t, b1, bs1,
                                         hef, hsf, nullptr, nullptr,
                                         slotTok, slotGate);

    prep_w_k<<<dim3(32, 32, 1),  tb>>>(Ws2, ws2t);                        // 6
    prep_w_k<<<dim3(32, 32, NE), tb>>>(W2, w2t);                          // 7

    // 8: merged GEMM phase 2
    moe_gemm<2><<<gG, 256, SMEM_BYTES>>>(hef, hsf, w2t, ws2t, b2, bs2,
                                         nullptr, nullptr, eout, out,
                                         slotTok, slotGate);

    combine_k<<<NTOK, 256>>>(tokSlot, eout, out);                         // 9
    (void)in_sizes; (void)n_in;
}

// round 13
// speedup vs baseline: 4.4492x; 1.1600x over previous
#include <cuda_runtime.h>
#include <cuda_fp16.h>
#include <math.h>
#include <stdint.h>

// ---------------- static problem shape ----------------
#define NTOK 8192
#define DIM  1024
#define NE   7
#define CAP  2574            // int(NTOK*2/7*1.1)
#define YEXP 21              // ceil(CAP/128)
#define NBLK_E (NE * YEXP * 8)      // 1176 expert CTAs
#define NBLK_G (NBLK_E + 64 * 8)    // + 512 shared CTAs = 1688

// ---------------- scratch (device globals) ----------------
__device__ __half g_xf [NTOK * DIM];
__device__ __half g_hsf[NTOK * DIM];
__device__ __half g_hef[NE * CAP * DIM];
__device__ float  g_eout[NE * CAP * DIM];
__device__ __half g_w1t[NE * DIM * DIM];
__device__ __half g_w2t[NE * DIM * DIM];
__device__ __half g_ws1t[DIM * DIM];
__device__ __half g_ws2t[DIM * DIM];
__device__ int   g_tokE[NTOK * 2];
__device__ float g_tokG[NTOK * 2];
__device__ int   g_slotTok[NE * CAP];
__device__ float g_slotGate[NE * CAP];
__device__ int   g_tokSlot[NTOK * 2];

// ---------------- PTX helpers ----------------
__device__ __forceinline__ uint32_t smem_u32(const void* p) {
    uint32_t a;
    asm("{ .reg .u64 t; cvta.to.shared.u64 t, %1; cvt.u32.u64 %0, t; }" : "=r"(a) : "l"(p));
    return a;
}
#define SW128(x) ((x) ^ (((x) >> 3) & 0x70))
#define CP16(dst, src) asm volatile("cp.async.cg.shared.global [%0], [%1], 16;" :: "r"(dst), "l"(src))
#define CP_COMMIT() asm volatile("cp.async.commit_group;" ::: "memory")
#define CP_WAIT(n)  asm volatile("cp.async.wait_group %0;" :: "n"(n) : "memory")

#define LDSM4(R, a) \
    asm volatile("ldmatrix.sync.aligned.m8n8.x4.shared.b16 {%0,%1,%2,%3}, [%4];" \
        : "=r"((R)[0]), "=r"((R)[1]), "=r"((R)[2]), "=r"((R)[3]) : "r"(a))

#define MMA(C, A, B0, B1) \
    asm volatile("mma.sync.aligned.m16n8k16.row.col.f32.f16.f16.f32 " \
        "{%0,%1,%2,%3}, {%4,%5,%6,%7}, {%8,%9}, {%0,%1,%2,%3};" \
        : "+f"((C)[0]), "+f"((C)[1]), "+f"((C)[2]), "+f"((C)[3]) \
        : "r"((A)[0]), "r"((A)[1]), "r"((A)[2]), "r"((A)[3]), "r"(B0), "r"(B1))

// ---------------- smem: 3 stages x 32KB: A 16K | B 16K (128B rows, SW128) ----------------
#define STG_BYTES 32768u
#define NSTAGE    3
#define SMEM_BYTES (NSTAGE * 32768)
#define NCHUNK    (DIM / 64)
#define PF_DIST   2

// ---------------- merged GEMM, flat 1D grid of NBLK_G CTAs ----------------
// PHASE 1: A=xf (expert: gather via slotTok; shared: direct); out = relu -> hef/hsf (fp16)
// PHASE 2: A=hef/hsf; expert: gate*(v+b) -> eout; shared: v+b -> out
template <int PHASE>
__global__ __launch_bounds__(256, 2)
void moe_gemm(const __half* __restrict__ Ae, const __half* __restrict__ As,
              const __half* __restrict__ Be, const __half* __restrict__ Bs,
              const float* __restrict__ biasE_, const float* __restrict__ biasS_,
              __half* __restrict__ OhE, __half* __restrict__ OhS,
              float* __restrict__ OfE, float* __restrict__ OfS,
              const int* __restrict__ slotTok, const float* __restrict__ slotGate)
{
    // flat decode
    const int bid = blockIdx.x;
    const bool sh = (bid >= NBLK_E);
    int e, yt, xt;
    if (sh) {
        int r = bid - NBLK_E;
        e = 0; yt = r >> 3; xt = r & 7;
    } else {
        e = bid / (YEXP * 8);
        int r = bid % (YEXP * 8);
        yt = r >> 3; xt = r & 7;
    }
    const int m0 = yt * 128;
    const int n0 = xt * 128;

    // early-exit fully-empty expert tiles (dense FCFS fill => first slot empty => tile empty)
    if (!sh && __ldg(&slotTok[e * CAP + m0]) >= NTOK) return;

    extern __shared__ char smem[];
    const int tid  = threadIdx.x;
    const int wid  = tid >> 5;
    const int lane = tid & 31;
    const uint32_t sb = smem_u32(smem);

    const float* bias = sh ? biasS_ : (biasE_ + e * DIM);
    const __half* Bt  = sh ? Bs : (Be + ((size_t)e << 20));

    // ---- per-thread source rows for fill ----
    const int rA = tid & 127;
    const __half* src;
    if (tid < 128) {
        if (sh) {
            src = As + (size_t)(m0 + rA) * DIM;
        } else if (PHASE == 1) {
            int slot = m0 + rA;
            int tok  = (slot < CAP) ? __ldg(&slotTok[e * CAP + slot]) : NTOK;
            if (tok >= NTOK) tok = 0;
            src = Ae + (size_t)tok * DIM;
        } else {
            int r = m0 + rA; if (r > CAP - 1) r = CAP - 1;
            src = Ae + ((size_t)e * CAP + r) * DIM;
        }
    } else {
        src = Bt + (size_t)(n0 + rA) * DIM;
    }
    const uint32_t dstBase = (tid < 128) ? 0u : 16384u;
    const uint32_t rowOff  = (uint32_t)rA * 128u;

    auto fill = [&](int c) {
        uint32_t stg = sb + (uint32_t)(c % NSTAGE) * STG_BYTES + dstBase;
        const __half* s = src + c * 64;
#pragma unroll
        for (int q = 0; q < 8; q++)
            CP16(stg + SW128(rowOff + q * 16u), s + q * 8);
        CP_COMMIT();
    };

    // ---- warp tiling: 2 (m) x 4 (n) ----
    const int wm = (wid & 1) * 64;
    const int wn = (wid >> 1) * 32;

    const uint32_t aRowL = (uint32_t)(wm + ((lane >> 3) & 1) * 8 + (lane & 7));
    const uint32_t aOffL = (uint32_t)((lane >> 4) * 16);
    const uint32_t bRowL = (uint32_t)(wn + ((lane >> 4) & 1) * 8 + (lane & 7));
    const uint32_t bOffL = (uint32_t)(((lane >> 3) & 1) * 16);

    float acc[4][4][4];
#pragma unroll
    for (int i = 0; i < 4; i++)
#pragma unroll
        for (int j = 0; j < 4; j++)
#pragma unroll
            for (int q = 0; q < 4; q++) acc[i][j][q] = 0.f;

    fill(0); fill(1);
#pragma unroll 1
    for (int c = 0; c < NCHUNK; c++) {
        if (c < NCHUNK - 1) { CP_WAIT(1); } else { CP_WAIT(0); }
        __syncthreads();
        if (c + PF_DIST < NCHUNK) fill(c + PF_DIST);

        uint32_t stg = sb + (uint32_t)(c % NSTAGE) * STG_BYTES;

        uint32_t bf[2][4][2];
        uint32_t areg[2][4];

#pragma unroll
        for (int bt = 0; bt < 2; bt++) {
            uint32_t r4[4];
            LDSM4(r4, stg + 16384u + SW128((bRowL + bt * 16u) * 128u + bOffL));
            bf[0][bt * 2][0] = r4[0]; bf[0][bt * 2][1] = r4[1];
            bf[0][bt * 2 + 1][0] = r4[2]; bf[0][bt * 2 + 1][1] = r4[3];
        }
        LDSM4(areg[0], stg + SW128(aRowL * 128u + aOffL));

#pragma unroll
        for (int ks = 0; ks < 4; ks++) {
            const int bcur = ks & 1, bnxt = bcur ^ 1;
#pragma unroll
            for (int mt = 0; mt < 4; mt++) {
                const int ap = (ks * 4 + mt) & 1, an = ap ^ 1;
                if (mt == 0 && ks < 3) {
#pragma unroll
                    for (int bt = 0; bt < 2; bt++) {
                        uint32_t r4[4];
                        LDSM4(r4, stg + 16384u +
                              SW128((bRowL + bt * 16u) * 128u + bOffL + (ks + 1) * 32u));
                        bf[bnxt][bt * 2][0] = r4[0]; bf[bnxt][bt * 2][1] = r4[1];
                        bf[bnxt][bt * 2 + 1][0] = r4[2]; bf[bnxt][bt * 2 + 1][1] = r4[3];
                    }
                }
                if (mt < 3)
                    LDSM4(areg[an], stg + SW128((aRowL + (mt + 1) * 16u) * 128u + aOffL + ks * 32u));
                else if (ks < 3)
                    LDSM4(areg[an], stg + SW128(aRowL * 128u + aOffL + (ks + 1) * 32u));
#pragma unroll
                for (int nt = 0; nt < 4; nt++)
                    MMA(acc[mt][nt], areg[ap], bf[bcur][nt][0], bf[bcur][nt][1]);
            }
        }
    }

    // ---- epilogue ----
#pragma unroll
    for (int mt = 0; mt < 4; mt++) {
#pragma unroll
        for (int h = 0; h < 2; h++) {
            int rloc = wm + mt * 16 + (lane >> 2) + h * 8;
            int grow = m0 + rloc;

            bool   valid = true;
            size_t obase = 0;
            float  gate  = 0.f;
            if (sh) {
                obase = (size_t)grow * DIM;
            } else if (PHASE == 1) {
                valid = (grow < CAP);
                obase = ((size_t)e * CAP + (valid ? grow : 0)) * DIM;
            } else {
                valid = false;
                if (grow < CAP) {
                    int tok = __ldg(&slotTok[e * CAP + grow]);
                    if (tok < NTOK) {
                        gate  = __ldg(&slotGate[e * CAP + grow]);
                        obase = ((size_t)e * CAP + grow) * DIM;
                        valid = true;
                    }
                }
            }
            if (!valid) continue;

#pragma unroll
            for (int nt = 0; nt < 4; nt++) {
                int nc = n0 + wn + nt * 8 + (lane & 3) * 2;
                float v0 = acc[mt][nt][h * 2 + 0] + __ldg(&bias[nc]);
                float v1 = acc[mt][nt][h * 2 + 1] + __ldg(&bias[nc + 1]);
                if (PHASE == 1) {
                    v0 = fmaxf(v0, 0.f); v1 = fmaxf(v1, 0.f);
                    __half h0 = __float2half_rn(v0);
                    __half h1 = __float2half_rn(v1);
                    uint32_t hp = (uint32_t)*(ushort*)&h0 | ((uint32_t)*(ushort*)&h1 << 16);
                    __half* O = sh ? OhS : OhE;
                    *reinterpret_cast<uint32_t*>(O + obase + nc) = hp;
                } else if (sh) {
                    *reinterpret_cast<float2*>(OfS + obase + nc) = make_float2(v0, v1);
                } else {
                    *reinterpret_cast<float2*>(OfE + obase + nc) =
                        make_float2(gate * v0, gate * v1);
                }
            }
        }
    }
}

// ---------------- prep: transpose + fp16 weights (experts z<NE, shared z==NE) ----------------
__global__ void prep_w_k(const float* __restrict__ We, const float* __restrict__ Ws,
                         __half* __restrict__ Te, __half* __restrict__ Ts)
{
    __shared__ float tile[32][33];
    const int z = blockIdx.z;
    const bool sh = (z == NE);
    const size_t mo = sh ? 0 : ((size_t)z << 20);
    const float* Wm = (sh ? Ws : We) + mo;
    __half*      Tm = (sh ? Ts : Te) + mo;
    int n0 = blockIdx.x * 32, k0 = blockIdx.y * 32;
    for (int r = threadIdx.y; r < 32; r += 8)
        tile[r][threadIdx.x] = Wm[(size_t)(k0 + r) * DIM + n0 + threadIdx.x];
    __syncthreads();
    for (int r = threadIdx.y; r < 32; r += 8) {
        float v = tile[threadIdx.x][r];
        Tm[(size_t)(n0 + r) * DIM + k0 + threadIdx.x] = __float2half_rn(v);
    }
}

// ---------------- router (also produces fp16 x) ----------------
__global__ void router_k(const float* __restrict__ x, const float* __restrict__ noise,
                         const float* __restrict__ Wr, const float* __restrict__ br,
                         const float* __restrict__ Wn, const float* __restrict__ bn,
                         int* __restrict__ tokE, float* __restrict__ tokG,
                         __half* __restrict__ xf)
{
    int gw   = (blockIdx.x * blockDim.x + threadIdx.x) >> 5;
    int lane = threadIdx.x & 31;
    if (gw >= NTOK) return;
    const float* xr = x + (size_t)gw * DIM;
    __half*      xo = xf + (size_t)gw * DIM;
    float aR[NE], aN[NE];
#pragma unroll
    for (int e = 0; e < NE; e++) { aR[e] = 0.f; aN[e] = 0.f; }
    for (int kk = 0; kk < DIM / 32; ++kk) {
        int   k  = kk * 32 + lane;
        float xv = xr[k];
        xo[k] = __float2half_rn(xv);
        const float* wr = Wr + (size_t)k * NE;
        const float* wn = Wn + (size_t)k * NE;
#pragma unroll
        for (int e = 0; e < NE; e++) {
            aR[e] = fmaf(xv, __ldg(wr + e), aR[e]);
            aN[e] = fmaf(xv, __ldg(wn + e), aN[e]);
        }
    }
#pragma unroll
    for (int off = 16; off; off >>= 1) {
#pragma unroll
        for (int e = 0; e < NE; e++) {
            aR[e] += __shfl_xor_sync(0xffffffffu, aR[e], off);
            aN[e] += __shfl_xor_sync(0xffffffffu, aN[e], off);
        }
    }
    if (lane == 0) {
        float v1 = -1e30f, v2 = -1e30f; int i1 = 0, i2 = 0;
#pragma unroll
        for (int e = 0; e < NE; e++) {
            float ln = aN[e] + bn[e];
            float sp = fmaxf(ln, 0.f) + log1pf(expf(-fabsf(ln)));
            float v  = aR[e] + br[e] + noise[(size_t)gw * NE + e] * sp;
            if (v > v1)      { v2 = v1; i2 = i1; v1 = v; i1 = e; }
            else if (v > v2) { v2 = v;  i2 = e; }
        }
        float d = expf(v2 - v1);
        float inv = 1.f / (1.f + d);
        tokE[2 * gw] = i1; tokE[2 * gw + 1] = i2;
        tokG[2 * gw] = inv; tokG[2 * gw + 1] = d * inv;
    }
}

// ---------------- load-balance loss ----------------
__global__ void lbl_k(const int* __restrict__ tokE, const float* __restrict__ tokG,
                      float* __restrict__ out, int writeLbl)
{
    __shared__ float ws[32][2 * NE];
    int tid = threadIdx.x, lane = tid & 31, wid = tid >> 5;
    float pg[NE], pc[NE];
#pragma unroll
    for (int e = 0; e < NE; e++) { pg[e] = 0.f; pc[e] = 0.f; }
    for (int t = tid; t < NTOK; t += 1024) {
        int   e0 = tokE[2 * t], e1 = tokE[2 * t + 1];
        float g0 = tokG[2 * t], g1 = tokG[2 * t + 1];
#pragma unroll
        for (int e = 0; e < NE; e++) {
            pg[e] += (e0 == e ? g0 : 0.f) + (e1 == e ? g1 : 0.f);
            pc[e] += (e0 == e ? 1.f : 0.f) + (e1 == e ? 1.f : 0.f);
        }
    }
#pragma unroll
    for (int off = 16; off; off >>= 1) {
#pragma unroll
        for (int e = 0; e < NE; e++) {
            pg[e] += __shfl_xor_sync(0xffffffffu, pg[e], off);
            pc[e] += __shfl_xor_sync(0xffffffffu, pc[e], off);
        }
    }
    if (lane == 0) {
#pragma unroll
        for (int e = 0; e < NE; e++) { ws[wid][e] = pg[e]; ws[wid][NE + e] = pc[e]; }
    }
    __syncthreads();
    if (tid == 0 && writeLbl) {
        float sums[2 * NE];
#pragma unroll
        for (int j = 0; j < 2 * NE; j++) {
            float s = 0.f;
            for (int w = 0; w < 32; w++) s += ws[w][j];
            sums[j] = s;
        }
        float l = 0.f;
        for (int e = 0; e < NE; e++)
            l += (sums[e] / (float)NTOK) * (sums[NE + e] / (float)NTOK);
        out[(size_t)NTOK * DIM] = l * (float)NE;
    }
}

// ---------------- capacity dispatch ----------------
__global__ void scan_k(const int* __restrict__ tokE, const float* __restrict__ tokG,
                       int* __restrict__ slotTok, float* __restrict__ slotGate,
                       int* __restrict__ tokSlot)
{
    const int e = blockIdx.x, tid = threadIdx.x;
    const int lane = tid & 31, wid = tid >> 5;
    __shared__ int wsum[32];
    __shared__ int wbase[32];
    __shared__ int blksum;

    for (int c = tid; c < CAP; c += 1024) {
        slotTok[e * CAP + c]  = NTOK;
        slotGate[e * CAP + c] = 0.f;
    }
    __syncthreads();

    int base = 0;
    for (int tile = 0; tile < NTOK; tile += 1024) {
        int t  = tile + tid;
        int e0 = tokE[2 * t], e1 = tokE[2 * t + 1];
        int flag = (e0 == e) || (e1 == e);
        uint32_t b = __ballot_sync(0xffffffffu, flag);
        int lpre = __popc(b & ((1u << lane) - 1));
        if (lane == 0) wsum[wid] = __popc(b);
        __syncthreads();
        if (wid == 0) {
            int v = wsum[lane];
            int inc = v;
#pragma unroll
            for (int off = 1; off < 32; off <<= 1) {
                int y = __shfl_up_sync(0xffffffffu, inc, off);
                if (lane >= off) inc += y;
            }
            wbase[lane] = inc - v;
            if (lane == 31) blksum = inc;
        }
        __syncthreads();
        int pos = base + wbase[wid] + lpre;
        if (flag) {
            int k = (e0 == e) ? 0 : 1;
            if (pos < CAP) {
                slotTok[e * CAP + pos]  = t;
                slotGate[e * CAP + pos] = (e0 == e) ? tokG[2 * t] : tokG[2 * t + 1];
                tokSlot[2 * t + k] = e * CAP + pos;
            } else {
                tokSlot[2 * t + k] = -1;
            }
        }
        base += blksum;
        __syncthreads();
    }
}

// ---------------- combine ----------------
__global__ void combine_k(const int* __restrict__ tokSlot,
                          const float* __restrict__ eout, float* __restrict__ out)
{
    int t = blockIdx.x;
    int d = threadIdx.x * 4;
    int s0 = __ldg(&tokSlot[2 * t]);
    int s1 = __ldg(&tokSlot[2 * t + 1]);
    float4 v = *reinterpret_cast<float4*>(out + (size_t)t * DIM + d);
    if (s0 >= 0) {
        float4 a = *reinterpret_cast<const float4*>(eout + (size_t)s0 * DIM + d);
        v.x += a.x; v.y += a.y; v.z += a.z; v.w += a.w;
    }
    if (s1 >= 0) {
        float4 a = *reinterpret_cast<const float4*>(eout + (size_t)s1 * DIM + d);
        v.x += a.x; v.y += a.y; v.z += a.z; v.w += a.w;
    }
    *reinterpret_cast<float4*>(out + (size_t)t * DIM + d) = v;
}

// ---------------- host ----------------
extern "C" void kernel_launch(void* const* d_in, const int* in_sizes, int n_in,
                              void* d_out, int out_size)
{
    const float* x   = (const float*)d_in[0];
    const float* noi = (const float*)d_in[1];
    const float* Wr  = (const float*)d_in[2];
    const float* br  = (const float*)d_in[3];
    const float* Wn  = (const float*)d_in[4];
    const float* bn  = (const float*)d_in[5];
    const float* W1  = (const float*)d_in[6];
    const float* b1  = (const float*)d_in[7];
    const float* W2  = (const float*)d_in[8];
    const float* b2  = (const float*)d_in[9];
    const float* Ws1 = (const float*)d_in[10];
    const float* bs1 = (const float*)d_in[11];
    const float* Ws2 = (const float*)d_in[12];
    const float* bs2 = (const float*)d_in[13];
    float* out = (float*)d_out;

    __half *xf, *hsf, *hef, *w1t, *w2t, *ws1t, *ws2t;
    float *eout;
    int *tokE, *slotTok, *tokSlot; float *tokG, *slotGate;
    cudaGetSymbolAddress((void**)&xf, g_xf);
    cudaGetSymbolAddress((void**)&hsf, g_hsf);
    cudaGetSymbolAddress((void**)&hef, g_hef);
    cudaGetSymbolAddress((void**)&eout, g_eout);
    cudaGetSymbolAddress((void**)&w1t, g_w1t);
    cudaGetSymbolAddress((void**)&w2t, g_w2t);
    cudaGetSymbolAddress((void**)&ws1t, g_ws1t);
    cudaGetSymbolAddress((void**)&ws2t, g_ws2t);
    cudaGetSymbolAddress((void**)&tokE, g_tokE); cudaGetSymbolAddress((void**)&tokG, g_tokG);
    cudaGetSymbolAddress((void**)&slotTok, g_slotTok); cudaGetSymbolAddress((void**)&slotGate, g_slotGate);
    cudaGetSymbolAddress((void**)&tokSlot, g_tokSlot);

    cudaFuncSetAttribute(moe_gemm<1>, cudaFuncAttributeMaxDynamicSharedMemorySize, SMEM_BYTES);
    cudaFuncSetAttribute(moe_gemm<2>, cudaFuncAttributeMaxDynamicSharedMemorySize, SMEM_BYTES);

    dim3 tb(32, 8);
    dim3 gW(32, 32, NE + 1);

    router_k<<<1024, 256>>>(x, noi, Wr, br, Wn, bn, tokE, tokG, xf);        // 0
    prep_w_k<<<gW, tb>>>(W1, Ws1, w1t, ws1t);                               // 1
    scan_k<<<NE, 1024>>>(tokE, tokG, slotTok, slotGate, tokSlot);           // 2

    // 3: merged GEMM phase 1  (this is the ncu-profiled launch)
    moe_gemm<1><<<NBLK_G, 256, SMEM_BYTES>>>(xf, xf, w1t, ws1t, b1, bs1,
                                             hef, hsf, nullptr, nullptr,
                                             slotTok, slotGate);

    lbl_k<<<1, 1024>>>(tokE, tokG, out, (out_size > NTOK * DIM) ? 1 : 0);   // 4
    prep_w_k<<<gW, tb>>>(W2, Ws2, w2t, ws2t);                               // 5

    // 6: merged GEMM phase 2
    moe_gemm<2><<<NBLK_G, 256, SMEM_BYTES>>>(hef, hsf, w2t, ws2t, b2, bs2,
                                             nullptr, nullptr, eout, out,
                                             slotTok, slotGate);

    combine_k<<<NTOK, 256>>>(tokSlot, eout, out);                           // 7
    (void)in_sizes; (void)n_in;
}

// round 14
// speedup vs baseline: 4.4580x; 1.0020x over previous
#include <cuda_runtime.h>
#include <cuda_fp16.h>
#include <math.h>
#include <stdint.h>

// ---------------- static problem shape ----------------
#define NTOK 8192
#define DIM  1024
#define NE   7
#define CAP  2574            // int(NTOK*2/7*1.1)
#define YEXP 21              // ceil(CAP/128)
#define NBLK_E (NE * YEXP * 8)      // 1176 expert CTAs
#define NBLK_G (NBLK_E + 64 * 8)    // + 512 shared CTAs = 1688

// ---------------- scratch (device globals) ----------------
__device__ __half g_xf [NTOK * DIM];
__device__ __half g_hsf[NTOK * DIM];
__device__ __half g_hef[NE * CAP * DIM];
__device__ float  g_eout[NE * CAP * DIM];
__device__ __half g_w1t[NE * DIM * DIM];
__device__ __half g_w2t[NE * DIM * DIM];
__device__ __half g_ws1t[DIM * DIM];
__device__ __half g_ws2t[DIM * DIM];
__device__ int   g_tokE[NTOK * 2];
__device__ float g_tokG[NTOK * 2];
__device__ int   g_slotTok[NE * CAP];
__device__ float g_slotGate[NE * CAP];
__device__ int   g_tokSlot[NTOK * 2];

// ---------------- PTX helpers ----------------
__device__ __forceinline__ uint32_t smem_u32(const void* p) {
    uint32_t a;
    asm("{ .reg .u64 t; cvta.to.shared.u64 t, %1; cvt.u32.u64 %0, t; }" : "=r"(a) : "l"(p));
    return a;
}
#define SW128(x) ((x) ^ (((x) >> 3) & 0x70))
#define CP16(dst, src) asm volatile("cp.async.cg.shared.global [%0], [%1], 16;" :: "r"(dst), "l"(src))
#define CP_COMMIT() asm volatile("cp.async.commit_group;" ::: "memory")
#define CP_WAIT(n)  asm volatile("cp.async.wait_group %0;" :: "n"(n) : "memory")

#define LDSM4(R, a) \
    asm volatile("ldmatrix.sync.aligned.m8n8.x4.shared.b16 {%0,%1,%2,%3}, [%4];" \
        : "=r"((R)[0]), "=r"((R)[1]), "=r"((R)[2]), "=r"((R)[3]) : "r"(a))

#define MMA(C, A, B0, B1) \
    asm volatile("mma.sync.aligned.m16n8k16.row.col.f32.f16.f16.f32 " \
        "{%0,%1,%2,%3}, {%4,%5,%6,%7}, {%8,%9}, {%0,%1,%2,%3};" \
        : "+f"((C)[0]), "+f"((C)[1]), "+f"((C)[2]), "+f"((C)[3]) \
        : "r"((A)[0]), "r"((A)[1]), "r"((A)[2]), "r"((A)[3]), "r"(B0), "r"(B1))

// ---------------- smem: 3 stages x 32KB: A 16K | B 16K (128B rows, SW128) ----------------
#define STG_BYTES 32768u
#define NSTAGE    3
#define SMEM_BYTES (NSTAGE * 32768)
#define NCHUNK    (DIM / 64)
#define PF_DIST   2

// ---------------- merged GEMM, flat 1D grid ----------------
template <int PHASE>
__global__ __launch_bounds__(256, 2)
void moe_gemm(const __half* __restrict__ Ae, const __half* __restrict__ As,
              const __half* __restrict__ Be, const __half* __restrict__ Bs,
              const float* __restrict__ biasE_, const float* __restrict__ biasS_,
              __half* __restrict__ OhE, __half* __restrict__ OhS,
              float* __restrict__ OfE, float* __restrict__ OfS,
              const int* __restrict__ slotTok, const float* __restrict__ slotGate)
{
    const int bid = blockIdx.x;
    const bool sh = (bid >= NBLK_E);
    int e, yt, xt;
    if (sh) {
        int r = bid - NBLK_E;
        e = 0; yt = r >> 3; xt = r & 7;
    } else {
        e = bid / (YEXP * 8);
        int r = bid % (YEXP * 8);
        yt = r >> 3; xt = r & 7;
    }
    const int m0 = yt * 128;
    const int n0 = xt * 128;

    if (!sh && __ldg(&slotTok[e * CAP + m0]) >= NTOK) return;

    extern __shared__ char smem[];
    const int tid  = threadIdx.x;
    const int wid  = tid >> 5;
    const int lane = tid & 31;
    const uint32_t sb = smem_u32(smem);

    const float* bias = sh ? biasS_ : (biasE_ + e * DIM);
    const __half* Bt  = sh ? Bs : (Be + ((size_t)e << 20));

    // ---- per-thread source rows for fill ----
    const int rA = tid & 127;
    const __half* src;
    if (tid < 128) {
        if (sh) {
            src = As + (size_t)(m0 + rA) * DIM;
        } else if (PHASE == 1) {
            int slot = m0 + rA;
            int tok  = (slot < CAP) ? __ldg(&slotTok[e * CAP + slot]) : NTOK;
            if (tok >= NTOK) tok = 0;
            src = Ae + (size_t)tok * DIM;
        } else {
            int r = m0 + rA; if (r > CAP - 1) r = CAP - 1;
            src = Ae + ((size_t)e * CAP + r) * DIM;
        }
    } else {
        src = Bt + (size_t)(n0 + rA) * DIM;
    }
    const uint32_t dstBase = (tid < 128) ? 0u : 16384u;
    const uint32_t rowOff  = (uint32_t)rA * 128u;

    auto fill = [&](int c) {
        uint32_t stg = sb + (uint32_t)(c % NSTAGE) * STG_BYTES + dstBase;
        const __half* s = src + c * 64;
#pragma unroll
        for (int q = 0; q < 8; q++)
            CP16(stg + SW128(rowOff + q * 16u), s + q * 8);
        CP_COMMIT();
    };

    // ---- warp tiling: 2 (m) x 4 (n) ----
    const int wm = (wid & 1) * 64;
    const int wn = (wid >> 1) * 32;

    const uint32_t aRowL = (uint32_t)(wm + ((lane >> 3) & 1) * 8 + (lane & 7));
    const uint32_t aOffL = (uint32_t)((lane >> 4) * 16);
    const uint32_t bRowL = (uint32_t)(wn + ((lane >> 4) & 1) * 8 + (lane & 7));
    const uint32_t bOffL = (uint32_t)(((lane >> 3) & 1) * 16);

    float acc[4][4][4];
#pragma unroll
    for (int i = 0; i < 4; i++)
#pragma unroll
        for (int j = 0; j < 4; j++)
#pragma unroll
            for (int q = 0; q < 4; q++) acc[i][j][q] = 0.f;

    fill(0); fill(1);
#pragma unroll 1
    for (int c = 0; c < NCHUNK; c++) {
        if (c < NCHUNK - 1) { CP_WAIT(1); } else { CP_WAIT(0); }
        __syncthreads();
        if (c + PF_DIST < NCHUNK) fill(c + PF_DIST);

        uint32_t stg  = sb + (uint32_t)(c % NSTAGE) * STG_BYTES;
        uint32_t stgB = stg + 16384u;

        uint32_t bf[2][4][2];
        uint32_t areg[3][4];      // triple buffer: prefetch distance 2 mt-steps

        // prologue: B(ks=0) -> bf[0]; A steps 0,1 -> areg[0], areg[1]
#pragma unroll
        for (int bt = 0; bt < 2; bt++) {
            uint32_t r4[4];
            LDSM4(r4, stgB + SW128((bRowL + bt * 16u) * 128u + bOffL));
            bf[0][bt * 2][0] = r4[0]; bf[0][bt * 2][1] = r4[1];
            bf[0][bt * 2 + 1][0] = r4[2]; bf[0][bt * 2 + 1][1] = r4[3];
        }
        LDSM4(areg[0], stg + SW128(aRowL * 128u + aOffL));
        LDSM4(areg[1], stg + SW128((aRowL + 16u) * 128u + aOffL));

#pragma unroll
        for (int ks = 0; ks < 4; ks++) {
            const int bcur = ks & 1, bnxt = bcur ^ 1;
#pragma unroll
            for (int mt = 0; mt < 4; mt++) {
                const int slot = ks * 4 + mt;
                const int ap = slot % 3;
                if (mt == 0 && ks < 3) {
#pragma unroll
                    for (int bt = 0; bt < 2; bt++) {
                        uint32_t r4[4];
                        LDSM4(r4, stgB +
                              SW128((bRowL + bt * 16u) * 128u + bOffL + (ks + 1) * 32u));
                        bf[bnxt][bt * 2][0] = r4[0]; bf[bnxt][bt * 2][1] = r4[1];
                        bf[bnxt][bt * 2 + 1][0] = r4[2]; bf[bnxt][bt * 2 + 1][1] = r4[3];
                    }
                }
                // prefetch A two mt-steps ahead
                {
                    const int ns = slot + 2;
                    if (ns < 16) {
                        const int nk = ns >> 2, nm = ns & 3;
                        LDSM4(areg[ns % 3],
                              stg + SW128((aRowL + nm * 16u) * 128u + aOffL + nk * 32u));
                    }
                }
#pragma unroll
                for (int nt = 0; nt < 4; nt++)
                    MMA(acc[mt][nt], areg[ap], bf[bcur][nt][0], bf[bcur][nt][1]);
            }
        }
    }

    // ---- epilogue ----
#pragma unroll
    for (int mt = 0; mt < 4; mt++) {
#pragma unroll
        for (int h = 0; h < 2; h++) {
            int rloc = wm + mt * 16 + (lane >> 2) + h * 8;
            int grow = m0 + rloc;

            bool   valid = true;
            size_t obase = 0;
            float  gate  = 0.f;
            if (sh) {
                obase = (size_t)grow * DIM;
            } else if (PHASE == 1) {
                valid = (grow < CAP);
                obase = ((size_t)e * CAP + (valid ? grow : 0)) * DIM;
            } else {
                valid = false;
                if (grow < CAP) {
                    int tok = __ldg(&slotTok[e * CAP + grow]);
                    if (tok < NTOK) {
                        gate  = __ldg(&slotGate[e * CAP + grow]);
                        obase = ((size_t)e * CAP + grow) * DIM;
                        valid = true;
                    }
                }
            }
            if (!valid) continue;

#pragma unroll
            for (int nt = 0; nt < 4; nt++) {
                int nc = n0 + wn + nt * 8 + (lane & 3) * 2;
                float v0 = acc[mt][nt][h * 2 + 0] + __ldg(&bias[nc]);
                float v1 = acc[mt][nt][h * 2 + 1] + __ldg(&bias[nc + 1]);
                if (PHASE == 1) {
                    v0 = fmaxf(v0, 0.f); v1 = fmaxf(v1, 0.f);
                    __half h0 = __float2half_rn(v0);
                    __half h1 = __float2half_rn(v1);
                    uint32_t hp = (uint32_t)*(ushort*)&h0 | ((uint32_t)*(ushort*)&h1 << 16);
                    __half* O = sh ? OhS : OhE;
                    *reinterpret_cast<uint32_t*>(O + obase + nc) = hp;
                } else if (sh) {
                    *reinterpret_cast<float2*>(OfS + obase + nc) = make_float2(v0, v1);
                } else {
                    *reinterpret_cast<float2*>(OfE + obase + nc) =
                        make_float2(gate * v0, gate * v1);
                }
            }
        }
    }
}

// ---------------- prep: transpose + fp16 weights (experts z<NE, shared z==NE) ----------------
__global__ void prep_w_k(const float* __restrict__ We, const float* __restrict__ Ws,
                         __half* __restrict__ Te, __half* __restrict__ Ts)
{
    __shared__ float tile[32][33];
    const int z = blockIdx.z;
    const bool sh = (z == NE);
    const size_t mo = sh ? 0 : ((size_t)z << 20);
    const float* Wm = (sh ? Ws : We) + mo;
    __half*      Tm = (sh ? Ts : Te) + mo;
    int n0 = blockIdx.x * 32, k0 = blockIdx.y * 32;
    for (int r = threadIdx.y; r < 32; r += 8)
        tile[r][threadIdx.x] = Wm[(size_t)(k0 + r) * DIM + n0 + threadIdx.x];
    __syncthreads();
    for (int r = threadIdx.y; r < 32; r += 8) {
        float v = tile[threadIdx.x][r];
        Tm[(size_t)(n0 + r) * DIM + k0 + threadIdx.x] = __float2half_rn(v);
    }
}

// ---------------- router (also produces fp16 x) ----------------
__global__ void router_k(const float* __restrict__ x, const float* __restrict__ noise,
                         const float* __restrict__ Wr, const float* __restrict__ br,
                         const float* __restrict__ Wn, const float* __restrict__ bn,
                         int* __restrict__ tokE, float* __restrict__ tokG,
                         __half* __restrict__ xf)
{
    int gw   = (blockIdx.x * blockDim.x + threadIdx.x) >> 5;
    int lane = threadIdx.x & 31;
    if (gw >= NTOK) return;
    const float* xr = x + (size_t)gw * DIM;
    __half*      xo = xf + (size_t)gw * DIM;
    float aR[NE], aN[NE];
#pragma unroll
    for (int e = 0; e < NE; e++) { aR[e] = 0.f; aN[e] = 0.f; }
    for (int kk = 0; kk < DIM / 32; ++kk) {
        int   k  = kk * 32 + lane;
        float xv = xr[k];
        xo[k] = __float2half_rn(xv);
        const float* wr = Wr + (size_t)k * NE;
        const float* wn = Wn + (size_t)k * NE;
#pragma unroll
        for (int e = 0; e < NE; e++) {
            aR[e] = fmaf(xv, __ldg(wr + e), aR[e]);
            aN[e] = fmaf(xv, __ldg(wn + e), aN[e]);
        }
    }
#pragma unroll
    for (int off = 16; off; off >>= 1) {
#pragma unroll
        for (int e = 0; e < NE; e++) {
            aR[e] += __shfl_xor_sync(0xffffffffu, aR[e], off);
            aN[e] += __shfl_xor_sync(0xffffffffu, aN[e], off);
        }
    }
    if (lane == 0) {
        float v1 = -1e30f, v2 = -1e30f; int i1 = 0, i2 = 0;
#pragma unroll
        for (int e = 0; e < NE; e++) {
            float ln = aN[e] + bn[e];
            float sp = fmaxf(ln, 0.f) + log1pf(expf(-fabsf(ln)));
            float v  = aR[e] + br[e] + noise[(size_t)gw * NE + e] * sp;
            if (v > v1)      { v2 = v1; i2 = i1; v1 = v; i1 = e; }
            else if (v > v2) { v2 = v;  i2 = e; }
        }
        float d = expf(v2 - v1);
        float inv = 1.f / (1.f + d);
        tokE[2 * gw] = i1; tokE[2 * gw + 1] = i2;
        tokG[2 * gw] = inv; tokG[2 * gw + 1] = d * inv;
    }
}

// ---------------- load-balance loss ----------------
__global__ void lbl_k(const int* __restrict__ tokE, const float* __restrict__ tokG,
                      float* __restrict__ out, int writeLbl)
{
    __shared__ float ws[32][2 * NE];
    int tid = threadIdx.x, lane = tid & 31, wid = tid >> 5;
    float pg[NE], pc[NE];
#pragma unroll
    for (int e = 0; e < NE; e++) { pg[e] = 0.f; pc[e] = 0.f; }
    for (int t = tid; t < NTOK; t += 1024) {
        int   e0 = tokE[2 * t], e1 = tokE[2 * t + 1];
        float g0 = tokG[2 * t], g1 = tokG[2 * t + 1];
#pragma unroll
        for (int e = 0; e < NE; e++) {
            pg[e] += (e0 == e ? g0 : 0.f) + (e1 == e ? g1 : 0.f);
            pc[e] += (e0 == e ? 1.f : 0.f) + (e1 == e ? 1.f : 0.f);
        }
    }
#pragma unroll
    for (int off = 16; off; off >>= 1) {
#pragma unroll
        for (int e = 0; e < NE; e++) {
            pg[e] += __shfl_xor_sync(0xffffffffu, pg[e], off);
            pc[e] += __shfl_xor_sync(0xffffffffu, pc[e], off);
        }
    }
    if (lane == 0) {
#pragma unroll
        for (int e = 0; e < NE; e++) { ws[wid][e] = pg[e]; ws[wid][NE + e] = pc[e]; }
    }
    __syncthreads();
    if (tid == 0 && writeLbl) {
        float sums[2 * NE];
#pragma unroll
        for (int j = 0; j < 2 * NE; j++) {
            float s = 0.f;
            for (int w = 0; w < 32; w++) s += ws[w][j];
            sums[j] = s;
        }
        float l = 0.f;
        for (int e = 0; e < NE; e++)
            l += (sums[e] / (float)NTOK) * (sums[NE + e] / (float)NTOK);
        out[(size_t)NTOK * DIM] = l * (float)NE;
    }
}

// ---------------- capacity dispatch ----------------
__global__ void scan_k(const int* __restrict__ tokE, const float* __restrict__ tokG,
                       int* __restrict__ slotTok, float* __restrict__ slotGate,
                       int* __restrict__ tokSlot)
{
    const int e = blockIdx.x, tid = threadIdx.x;
    const int lane = tid & 31, wid = tid >> 5;
    __shared__ int wsum[32];
    __shared__ int wbase[32];
    __shared__ int blksum;

    for (int c = tid; c < CAP; c += 1024) {
        slotTok[e * CAP + c]  = NTOK;
        slotGate[e * CAP + c] = 0.f;
    }
    __syncthreads();

    int base = 0;
    for (int tile = 0; tile < NTOK; tile += 1024) {
        int t  = tile + tid;
        int e0 = tokE[2 * t], e1 = tokE[2 * t + 1];
        int flag = (e0 == e) || (e1 == e);
        uint32_t b = __ballot_sync(0xffffffffu, flag);
        int lpre = __popc(b & ((1u << lane) - 1));
        if (lane == 0) wsum[wid] = __popc(b);
        __syncthreads();
        if (wid == 0) {
            int v = wsum[lane];
            int inc = v;
#pragma unroll
            for (int off = 1; off < 32; off <<= 1) {
                int y = __shfl_up_sync(0xffffffffu, inc, off);
                if (lane >= off) inc += y;
            }
            wbase[lane] = inc - v;
            if (lane == 31) blksum = inc;
        }
        __syncthreads();
        int pos = base + wbase[wid] + lpre;
        if (flag) {
            int k = (e0 == e) ? 0 : 1;
            if (pos < CAP) {
                slotTok[e * CAP + pos]  = t;
                slotGate[e * CAP + pos] = (e0 == e) ? tokG[2 * t] : tokG[2 * t + 1];
                tokSlot[2 * t + k] = e * CAP + pos;
            } else {
                tokSlot[2 * t + k] = -1;
            }
        }
        base += blksum;
        __syncthreads();
    }
}

// ---------------- combine ----------------
__global__ void combine_k(const int* __restrict__ tokSlot,
                          const float* __restrict__ eout, float* __restrict__ out)
{
    int t = blockIdx.x;
    int d = threadIdx.x * 4;
    int s0 = __ldg(&tokSlot[2 * t]);
    int s1 = __ldg(&tokSlot[2 * t + 1]);
    float4 v = *reinterpret_cast<float4*>(out + (size_t)t * DIM + d);
    if (s0 >= 0) {
        float4 a = *reinterpret_cast<const float4*>(eout + (size_t)s0 * DIM + d);
        v.x += a.x; v.y += a.y; v.z += a.z; v.w += a.w;
    }
    if (s1 >= 0) {
        float4 a = *reinterpret_cast<const float4*>(eout + (size_t)s1 * DIM + d);
        v.x += a.x; v.y += a.y; v.z += a.z; v.w += a.w;
    }
    *reinterpret_cast<float4*>(out + (size_t)t * DIM + d) = v;
}

// ---------------- host ----------------
extern "C" void kernel_launch(void* const* d_in, const int* in_sizes, int n_in,
                              void* d_out, int out_size)
{
    const float* x   = (const float*)d_in[0];
    const float* noi = (const float*)d_in[1];
    const float* Wr  = (const float*)d_in[2];
    const float* br  = (const float*)d_in[3];
    const float* Wn  = (const float*)d_in[4];
    const float* bn  = (const float*)d_in[5];
    const float* W1  = (const float*)d_in[6];
    const float* b1  = (const float*)d_in[7];
    const float* W2  = (const float*)d_in[8];
    const float* b2  = (const float*)d_in[9];
    const float* Ws1 = (const float*)d_in[10];
    const float* bs1 = (const float*)d_in[11];
    const float* Ws2 = (const float*)d_in[12];
    const float* bs2 = (const float*)d_in[13];
    float* out = (float*)d_out;

    __half *xf, *hsf, *hef, *w1t, *w2t, *ws1t, *ws2t;
    float *eout;
    int *tokE, *slotTok, *tokSlot; float *tokG, *slotGate;
    cudaGetSymbolAddress((void**)&xf, g_xf);
    cudaGetSymbolAddress((void**)&hsf, g_hsf);
    cudaGetSymbolAddress((void**)&hef, g_hef);
    cudaGetSymbolAddress((void**)&eout, g_eout);
    cudaGetSymbolAddress((void**)&w1t, g_w1t);
    cudaGetSymbolAddress((void**)&w2t, g_w2t);
    cudaGetSymbolAddress((void**)&ws1t, g_ws1t);
    cudaGetSymbolAddress((void**)&ws2t, g_ws2t);
    cudaGetSymbolAddress((void**)&tokE, g_tokE); cudaGetSymbolAddress((void**)&tokG, g_tokG);
    cudaGetSymbolAddress((void**)&slotTok, g_slotTok); cudaGetSymbolAddress((void**)&slotGate, g_slotGate);
    cudaGetSymbolAddress((void**)&tokSlot, g_tokSlot);

    cudaFuncSetAttribute(moe_gemm<1>, cudaFuncAttributeMaxDynamicSharedMemorySize, SMEM_BYTES);
    cudaFuncSetAttribute(moe_gemm<2>, cudaFuncAttributeMaxDynamicSharedMemorySize, SMEM_BYTES);

    dim3 tb(32, 8);
    dim3 gW(32, 32, NE + 1);

    router_k<<<1024, 256>>>(x, noi, Wr, br, Wn, bn, tokE, tokG, xf);        // 0
    prep_w_k<<<gW, tb>>>(W1, Ws1, w1t, ws1t);                               // 1
    scan_k<<<NE, 1024>>>(tokE, tokG, slotTok, slotGate, tokSlot);           // 2

    // 3: merged GEMM phase 1  (ncu-profiled launch)
    moe_gemm<1><<<NBLK_G, 256, SMEM_BYTES>>>(xf, xf, w1t, ws1t, b1, bs1,
                                             hef, hsf, nullptr, nullptr,
                                             slotTok, slotGate);

    lbl_k<<<1, 1024>>>(tokE, tokG, out, (out_size > NTOK * DIM) ? 1 : 0);   // 4
    prep_w_k<<<gW, tb>>>(W2, Ws2, w2t, ws2t);                               // 5

    // 6: merged GEMM phase 2
    moe_gemm<2><<<NBLK_G, 256, SMEM_BYTES>>>(hef, hsf, w2t, ws2t, b2, bs2,
                                             nullptr, nullptr, eout, out,
                                             slotTok, slotGate);

    combine_k<<<NTOK, 256>>>(tokSlot, eout, out);                           // 7
    (void)in_sizes; (void)n_in;
}